// round 10
// baseline (speedup 1.0000x reference)
#include <cuda_runtime.h>
#include <cuda_fp16.h>
#include <math.h>
#include <stdint.h>

#define NMAX 100000
#define EMAX 3200000
#define RREL 15
#define NLAY 4
#define NB16 (NMAX * 16)

__device__ __half g_S[(size_t)NMAX * 544];
__device__ __half g_x16[NMAX * 36];
__device__ __half g_Wcat[4 * 544 * 32];
__device__ float g_x0[NMAX * 36];
__device__ float g_x[NMAX * 32];
__device__ float g_h[NMAX * 32];
__device__ float g_qv[NMAX * 16];
__device__ float g_kv[NMAX * 16];
__device__ float g_alpha[EMAX];
__device__ int   g_rowptr16[NB16 + 1];
__device__ int   g_cursor16[NB16];
__device__ int   g_count16[NB16];
__device__ int   g_epack[EMAX];
__device__ int   g_bsum[6400];
__device__ int   g_boff[6400];
__device__ float g_wq[NLAY][RREL][36];
__device__ float g_wk[NLAY][RREL][36];
__device__ double g_stats[NLAY][2];
__device__ double g_pool[32];
__device__ double g_psum[3];
__device__ double g_M[6];
__device__ unsigned int g_mnkey[3], g_mxkey[3];
__device__ float  g_pmean[3];
__device__ float g_V[9];
__device__ float g_pscale;
__device__ double g_fstats[2];
__device__ float  g_fp[2];

__device__ __forceinline__ double warpSumD(double v) {
    for (int o = 16; o > 0; o >>= 1) v += __shfl_down_sync(0xffffffffu, v, o);
    return v;
}
__device__ __forceinline__ float warpSumF(float v) {
    for (int o = 16; o > 0; o >>= 1) v += __shfl_xor_sync(0xffffffffu, v, o);
    return v;
}
__device__ __forceinline__ unsigned int fkey(float f) {
    unsigned int u = __float_as_uint(f);
    return (u & 0x80000000u) ? ~u : (u | 0x80000000u);
}
__device__ __forceinline__ float funkey(unsigned int k) {
    return (k & 0x80000000u) ? __uint_as_float(k ^ 0x80000000u) : __uint_as_float(~k);
}

__device__ __forceinline__ void mma16816(float& d0, float& d1, float& d2, float& d3,
    uint32_t a0, uint32_t a1, uint32_t a2, uint32_t a3, uint32_t b0, uint32_t b1) {
    asm volatile("mma.sync.aligned.m16n8k16.row.col.f32.f16.f16.f32 "
        "{%0,%1,%2,%3}, {%4,%5,%6,%7}, {%8,%9}, {%0,%1,%2,%3};"
        : "+f"(d0), "+f"(d1), "+f"(d2), "+f"(d3)
        : "r"(a0), "r"(a1), "r"(a2), "r"(a3), "r"(b0), "r"(b1));
}

// Weight prep: Wcat (fp16, [l][kk][o]) + wq/wk. Data-independent.
__global__ void k_wprep(const float* __restrict__ W0, const float* __restrict__ q0,
                        const float* __restrict__ k0, const float* __restrict__ Ws,
                        const float* __restrict__ qs, const float* __restrict__ ks) {
    int idx = blockIdx.x * blockDim.x + threadIdx.x;
    const int WCN = 4 * 544 * 32;
    if (idx < WCN) {
        int l = idx / (544 * 32);
        int rem = idx % (544 * 32);
        int kk = rem >> 5, o = rem & 31;
        int F = (l == 0) ? 35 : 32, FP = (l == 0) ? 36 : 32;
        float val = 0.f;
        if (kk < RREL * FP) {
            int r = kk / FP, f = kk % FP;
            if (f < F) {
                const float* W = (l == 0) ? W0 : Ws + (size_t)(l - 1) * RREL * 32 * 32;
                val = W[((size_t)r * F + f) * 32 + o];
            }
        }
        g_Wcat[idx] = __float2half(val);
    } else if (idx < WCN + 4 * RREL * 36) {
        int j = idx - WCN;
        int l = j / (RREL * 36);
        int rem = j % (RREL * 36);
        int r = rem / 36, f = rem % 36;
        int F = (l == 0) ? 35 : 32;
        float sq = 0.f, sk = 0.f;
        if (f < F) {
            const float* W = (l == 0) ? W0 : Ws + (size_t)(l - 1) * RREL * 32 * 32;
            const float* q = (l == 0) ? q0 : qs + (l - 1) * 32;
            const float* kk2 = (l == 0) ? k0 : ks + (l - 1) * 32;
            const float* row = W + ((size_t)r * F + f) * 32;
            for (int o = 0; o < 32; o++) { sq += row[o] * q[o]; sk += row[o] * kk2[o]; }
        }
        g_wq[l][r][f] = sq;
        g_wk[l][r][f] = sk;
    }
}

__global__ void k_zero() {
    int i = blockIdx.x * blockDim.x + threadIdx.x;
    int stride = gridDim.x * blockDim.x;
    for (int j = i; j < NB16; j += stride) g_count16[j] = 0;
    if (i == 0) {
        for (int l = 0; l < NLAY; l++) { g_stats[l][0] = 0.0; g_stats[l][1] = 0.0; }
        for (int o = 0; o < 32; o++) g_pool[o] = 0.0;
        for (int c = 0; c < 3; c++) { g_psum[c] = 0.0; g_mnkey[c] = 0xFFFFFFFFu; g_mxkey[c] = 0u; }
        for (int c = 0; c < 6; c++) g_M[c] = 0.0;
        g_fstats[0] = 0.0; g_fstats[1] = 0.0;
    }
}

__global__ void k_hist(const int* __restrict__ ei, const int* __restrict__ et, int e) {
    int i = blockIdx.x * blockDim.x + threadIdx.x;
    if (i < e) atomicAdd(&g_count16[ei[e + i] * 16 + et[i]], 1);
}

// Fused pstats + fstat
__global__ void k_stats(const float* __restrict__ d, int n) {
    double s0 = 0, s1 = 0, s2 = 0;
    double r00 = 0, r01 = 0, r02 = 0, r11 = 0, r12 = 0, r22 = 0;
    float mn0 = 3e38f, mn1 = 3e38f, mn2 = 3e38f;
    float mx0 = -3e38f, mx1 = -3e38f, mx2 = -3e38f;
    int gtid = blockIdx.x * blockDim.x + threadIdx.x;
    int stride = gridDim.x * blockDim.x;
    for (int i = gtid; i < n; i += stride) {
        float x = d[i * 35 + 0], y = d[i * 35 + 1], z = d[i * 35 + 2];
        double dx = x, dy = y, dz = z;
        s0 += dx; s1 += dy; s2 += dz;
        r00 += dx * dx; r01 += dx * dy; r02 += dx * dz;
        r11 += dy * dy; r12 += dy * dz; r22 += dz * dz;
        mn0 = fminf(mn0, x); mx0 = fmaxf(mx0, x);
        mn1 = fminf(mn1, y); mx1 = fmaxf(mx1, y);
        mn2 = fminf(mn2, z); mx2 = fmaxf(mx2, z);
    }
    double fs = 0, fss = 0;
    int total = n * 32;
    for (int i = gtid; i < total; i += stride) {
        double v = (double)d[(i >> 5) * 35 + 3 + (i & 31)];
        fs += v; fss += v * v;
    }
    s0 = warpSumD(s0); s1 = warpSumD(s1); s2 = warpSumD(s2);
    r00 = warpSumD(r00); r01 = warpSumD(r01); r02 = warpSumD(r02);
    r11 = warpSumD(r11); r12 = warpSumD(r12); r22 = warpSumD(r22);
    fs = warpSumD(fs); fss = warpSumD(fss);
    for (int o = 16; o > 0; o >>= 1) {
        mn0 = fminf(mn0, __shfl_down_sync(0xffffffffu, mn0, o));
        mn1 = fminf(mn1, __shfl_down_sync(0xffffffffu, mn1, o));
        mn2 = fminf(mn2, __shfl_down_sync(0xffffffffu, mn2, o));
        mx0 = fmaxf(mx0, __shfl_down_sync(0xffffffffu, mx0, o));
        mx1 = fmaxf(mx1, __shfl_down_sync(0xffffffffu, mx1, o));
        mx2 = fmaxf(mx2, __shfl_down_sync(0xffffffffu, mx2, o));
    }
    if ((threadIdx.x & 31) == 0) {
        atomicAdd(&g_psum[0], s0); atomicAdd(&g_psum[1], s1); atomicAdd(&g_psum[2], s2);
        atomicAdd(&g_M[0], r00); atomicAdd(&g_M[1], r01); atomicAdd(&g_M[2], r02);
        atomicAdd(&g_M[3], r11); atomicAdd(&g_M[4], r12); atomicAdd(&g_M[5], r22);
        atomicAdd(&g_fstats[0], fs); atomicAdd(&g_fstats[1], fss);
        atomicMin(&g_mnkey[0], fkey(mn0)); atomicMax(&g_mxkey[0], fkey(mx0));
        atomicMin(&g_mnkey[1], fkey(mn1)); atomicMax(&g_mxkey[1], fkey(mx1));
        atomicMin(&g_mnkey[2], fkey(mn2)); atomicMax(&g_mxkey[2], fkey(mx2));
    }
}

// ---- LAPACK dsyevd path (PASSING convention): dsytd2('L') -> dsteqr('I') -> V=Q*Z ----
__device__ void dev_dlartg(double f, double g, double* cs, double* sn, double* r) {
    if (g == 0.0) { *cs = 1.0; *sn = 0.0; *r = f; }
    else if (f == 0.0) { *cs = 0.0; *sn = 1.0; *r = g; }
    else {
        double rr = sqrt(f * f + g * g);
        double c = f / rr, s = g / rr;
        if (fabs(f) > fabs(g) && c < 0.0) { c = -c; s = -s; rr = -rr; }
        *cs = c; *sn = s; *r = rr;
    }
}

__device__ void dev_dlaev2(double a, double b, double c,
                           double* rt1, double* rt2, double* cs1, double* sn1) {
    double sm = a + c, df = a - c;
    double adf = fabs(df), tb = b + b, ab = fabs(tb);
    double acmx, acmn;
    if (fabs(a) > fabs(c)) { acmx = a; acmn = c; } else { acmx = c; acmn = a; }
    double rt;
    if (adf > ab) rt = adf * sqrt(1.0 + (ab / adf) * (ab / adf));
    else if (adf < ab) rt = ab * sqrt(1.0 + (adf / ab) * (adf / ab));
    else rt = ab * sqrt(2.0);
    int sgn1;
    if (sm < 0.0) { *rt1 = 0.5 * (sm - rt); sgn1 = -1; *rt2 = (acmx / *rt1) * acmn - (b / *rt1) * b; }
    else if (sm > 0.0) { *rt1 = 0.5 * (sm + rt); sgn1 = 1; *rt2 = (acmx / *rt1) * acmn - (b / *rt1) * b; }
    else { *rt1 = 0.5 * rt; *rt2 = -0.5 * rt; sgn1 = 1; }
    double cs; int sgn2;
    if (df >= 0.0) { cs = df + rt; sgn2 = 1; } else { cs = df - rt; sgn2 = -1; }
    double acs = fabs(cs);
    if (acs > ab) {
        double ct = -tb / cs;
        *sn1 = 1.0 / sqrt(1.0 + ct * ct);
        *cs1 = ct * (*sn1);
    } else {
        if (ab == 0.0) { *cs1 = 1.0; *sn1 = 0.0; }
        else {
            double tn = -cs / tb;
            *cs1 = 1.0 / sqrt(1.0 + tn * tn);
            *sn1 = tn * (*cs1);
        }
    }
    if (sgn1 == sgn2) { double tn = *cs1; *cs1 = -(*sn1); *sn1 = tn; }
}

__global__ void k_eigh(int nn) {
    if (threadIdx.x != 0) return;
    double mu0 = g_psum[0] / (double)nn, mu1 = g_psum[1] / (double)nn, mu2 = g_psum[2] / (double)nn;
    g_pmean[0] = (float)mu0; g_pmean[1] = (float)mu1; g_pmean[2] = (float)mu2;
    {
        double cnt = (double)nn * 32.0;
        double mu = g_fstats[0] / cnt;
        double var = g_fstats[1] / cnt - mu * mu;
        if (var < 0.0) var = 0.0;
        g_fp[0] = (float)mu;
        g_fp[1] = (float)sqrt(var) + 1e-5f;
    }
    double mus[3] = {mu0, mu1, mu2};
    float mxab = 0.f;
    for (int c = 0; c < 3; c++) {
        float hi = funkey(g_mxkey[c]) - (float)mus[c];
        float lo = (float)mus[c] - funkey(g_mnkey[c]);
        mxab = fmaxf(mxab, fmaxf(hi, lo));
    }
    float sc = (1.0f / mxab) * 0.999999f;
    g_pscale = sc;
    double s2 = (double)sc * (double)sc;
    double N = (double)nn;
    double a00 = (g_M[0] - N * mu0 * mu0) * s2;
    double a01 = (g_M[1] - N * mu0 * mu1) * s2;
    double a02 = (g_M[2] - N * mu0 * mu2) * s2;
    double a11 = (g_M[3] - N * mu1 * mu1) * s2;
    double a12 = (g_M[4] - N * mu1 * mu2) * s2;
    double a22 = (g_M[5] - N * mu2 * mu2) * s2;

    double d[4], e[3];
    double tau = 0.0, v1 = 0.0;
    {
        double alpha = a01;
        double x = a02;
        double xnorm = fabs(x);
        double beta;
        if (xnorm == 0.0) { tau = 0.0; beta = alpha; }
        else {
            double hy = sqrt(alpha * alpha + xnorm * xnorm);
            beta = (alpha >= 0.0) ? -hy : hy;
            tau = (beta - alpha) / beta;
            v1 = x / (alpha - beta);
        }
        e[1] = beta;
        double nd11 = a11, nd12 = a12, nd22 = a22;
        if (tau != 0.0) {
            double w0 = tau * (a11 + a12 * v1);
            double w1 = tau * (a12 + a22 * v1);
            double al = -0.5 * tau * (w0 + w1 * v1);
            w0 += al;
            w1 += al * v1;
            nd11 = a11 - 2.0 * w0;
            nd12 = a12 - (w1 + w0 * v1);
            nd22 = a22 - 2.0 * v1 * w1;
        }
        d[1] = a00; d[2] = nd11; d[3] = nd22;
        e[2] = nd12;
    }

    const int n = 3;
    double Z[4][4];
    for (int i = 1; i <= 3; i++)
        for (int j = 1; j <= 3; j++) Z[i][j] = (i == j) ? 1.0 : 0.0;
    double eps = 2.220446049250313e-16;
    double eps2 = eps * eps;
    double safmin = 2.2250738585072014e-308;
    int nmaxit = n * 30, jtot = 0;
    double wc[4], ws[4];
    int l1 = 1;
    while (true) {
        if (l1 > n) break;
        if (l1 > 1) e[l1 - 1] = 0.0;
        int m;
        if (l1 <= n - 1) {
            for (m = l1; m <= n - 1; m++) {
                double tst = fabs(e[m]);
                if (tst == 0.0) break;
                if (tst <= (sqrt(fabs(d[m])) * sqrt(fabs(d[m + 1]))) * eps) { e[m] = 0.0; break; }
            }
        } else m = n;
        int l = l1, lend = m;
        l1 = m + 1;
        if (lend == l) continue;
        if (fabs(d[lend]) < fabs(d[l])) { int t = lend; lend = l; l = t; }
        if (lend > l) {
            while (true) {
                int mm;
                if (l != lend) {
                    for (mm = l; mm <= lend - 1; mm++) {
                        double tst = e[mm] * e[mm];
                        if (tst <= (eps2 * fabs(d[mm]) * fabs(d[mm + 1]) + safmin)) break;
                    }
                } else mm = lend;
                m = mm;
                if (m < lend) e[m] = 0.0;
                double p = d[l];
                if (m == l) { d[l] = p; l = l + 1; if (l <= lend) continue; else break; }
                if (m == l + 1) {
                    double rt1, rt2, c, s;
                    dev_dlaev2(d[l], e[l], d[l + 1], &rt1, &rt2, &c, &s);
                    for (int i = 1; i <= n; i++) {
                        double temp = Z[i][l + 1];
                        Z[i][l + 1] = c * temp - s * Z[i][l];
                        Z[i][l] = s * temp + c * Z[i][l];
                    }
                    d[l] = rt1; d[l + 1] = rt2; e[l] = 0.0;
                    l = l + 2;
                    if (l <= lend) continue; else break;
                }
                if (jtot == nmaxit) break;
                jtot++;
                double g = (d[l + 1] - p) / (2.0 * e[l]);
                double r = sqrt(g * g + 1.0);
                double sg = (g >= 0.0) ? fabs(r) : -fabs(r);
                g = d[m] - p + e[l] / (g + sg);
                double s = 1.0, c = 1.0;
                p = 0.0;
                for (int i = m - 1; i >= l; i--) {
                    double f = s * e[i];
                    double b = c * e[i];
                    dev_dlartg(g, f, &c, &s, &r);
                    if (i != m - 1) e[i + 1] = r;
                    g = d[i + 1] - p;
                    r = (d[i] - g) * s + 2.0 * c * b;
                    p = s * r;
                    d[i + 1] = g + p;
                    g = c * r - b;
                    wc[i] = c; ws[i] = -s;
                }
                for (int j = m - 1; j >= l; j--) {
                    double cj = wc[j], sj = ws[j];
                    for (int i = 1; i <= n; i++) {
                        double temp = Z[i][j + 1];
                        Z[i][j + 1] = cj * temp - sj * Z[i][j];
                        Z[i][j] = sj * temp + cj * Z[i][j];
                    }
                }
                d[l] = d[l] - p;
                e[l] = g;
            }
        } else {
            while (true) {
                int mm;
                if (l != lend) {
                    for (mm = l; mm >= lend + 1; mm--) {
                        double tst = e[mm - 1] * e[mm - 1];
                        if (tst <= (eps2 * fabs(d[mm]) * fabs(d[mm - 1]) + safmin)) break;
                    }
                } else mm = lend;
                m = mm;
                if (m > lend) e[m - 1] = 0.0;
                double p = d[l];
                if (m == l) { d[l] = p; l = l - 1; if (l >= lend) continue; else break; }
                if (m == l - 1) {
                    double rt1, rt2, c, s;
                    dev_dlaev2(d[l - 1], e[l - 1], d[l], &rt1, &rt2, &c, &s);
                    for (int i = 1; i <= n; i++) {
                        double temp = Z[i][l];
                        Z[i][l] = c * temp - s * Z[i][l - 1];
                        Z[i][l - 1] = s * temp + c * Z[i][l - 1];
                    }
                    d[l - 1] = rt1; d[l] = rt2; e[l - 1] = 0.0;
                    l = l - 2;
                    if (l >= lend) continue; else break;
                }
                if (jtot == nmaxit) break;
                jtot++;
                double g = (d[l - 1] - p) / (2.0 * e[l - 1]);
                double r = sqrt(g * g + 1.0);
                double sg = (g >= 0.0) ? fabs(r) : -fabs(r);
                g = d[m] - p + e[l - 1] / (g + sg);
                double s = 1.0, c = 1.0;
                p = 0.0;
                for (int i = m; i <= l - 1; i++) {
                    double f = s * e[i];
                    double b = c * e[i];
                    dev_dlartg(g, f, &c, &s, &r);
                    if (i != m) e[i - 1] = r;
                    g = d[i] - p;
                    r = (d[i + 1] - g) * s + 2.0 * c * b;
                    p = s * r;
                    d[i] = g + p;
                    g = c * r - b;
                    wc[i] = c; ws[i] = s;
                }
                for (int j = m; j <= l - 1; j++) {
                    double cj = wc[j], sj = ws[j];
                    for (int i = 1; i <= n; i++) {
                        double temp = Z[i][j + 1];
                        Z[i][j + 1] = cj * temp - sj * Z[i][j];
                        Z[i][j] = sj * temp + cj * Z[i][j];
                    }
                }
                d[l] = d[l] - p;
                e[l - 1] = g;
            }
        }
    }
    for (int ii = 2; ii <= n; ii++) {
        int i = ii - 1, k = i;
        double p = d[i];
        for (int j = ii; j <= n; j++) if (d[j] < p) { k = j; p = d[j]; }
        if (k != i) {
            d[k] = d[i]; d[i] = p;
            for (int rr = 1; rr <= n; rr++) { double t = Z[rr][i]; Z[rr][i] = Z[rr][k]; Z[rr][k] = t; }
        }
    }
    double Q[4][4];
    Q[1][1] = 1.0; Q[1][2] = 0.0; Q[1][3] = 0.0;
    Q[2][1] = 0.0; Q[3][1] = 0.0;
    Q[2][2] = 1.0 - tau;
    Q[2][3] = -tau * v1;
    Q[3][2] = -tau * v1;
    Q[3][3] = 1.0 - tau * v1 * v1;
    for (int i = 1; i <= 3; i++)
        for (int j = 1; j <= 3; j++) {
            double acc = 0.0;
            for (int k = 1; k <= 3; k++) acc += Q[i][k] * Z[k][j];
            g_V[(i - 1) * 3 + (j - 1)] = (float)acc;
        }
}

__global__ void k_buildx0(const float* __restrict__ d, const float* __restrict__ ln1w,
                          const float* __restrict__ ln1b, int n) {
    int idx = blockIdx.x * blockDim.x + threadIdx.x;
    if (idx >= n * 36) return;
    int node = idx / 36, j = idx % 36;
    float val;
    if (j < 3) {
        float sc = g_pscale;
        float a = (d[node * 35 + 0] - g_pmean[0]) * sc;
        float b = (d[node * 35 + 1] - g_pmean[1]) * sc;
        float c = (d[node * 35 + 2] - g_pmean[2]) * sc;
        val = a * g_V[0 + j] + b * g_V[3 + j] + c * g_V[6 + j];
    } else if (j < 35) {
        val = (d[node * 35 + j] - g_fp[0]) / g_fp[1] * ln1w[j - 3] + ln1b[j - 3];
    } else val = 0.f;
    g_x0[idx] = val;
    g_x16[idx] = __float2half(val);
}

__global__ void k_scanA(int ntot) {
    __shared__ int ws[8];
    int b = blockIdx.x, tid = threadIdx.x, lane = tid & 31, w = tid >> 5;
    int i = b * 256 + tid;
    int v = (i < ntot) ? g_count16[i] : 0;
    int x = v;
    for (int o = 1; o < 32; o <<= 1) {
        int y = __shfl_up_sync(0xffffffffu, x, o);
        if (lane >= o) x += y;
    }
    if (lane == 31) ws[w] = x;
    __syncthreads();
    if (tid == 0) {
        int run = 0;
        for (int j = 0; j < 8; j++) { int t = ws[j]; ws[j] = run; run += t; }
    }
    __syncthreads();
    int excl = x - v + ws[w];
    if (i < ntot) g_rowptr16[i] = excl;
    if (tid == 255) g_bsum[b] = excl + v;
}

__global__ void k_scanB(int nb, int ntot) {
    __shared__ int sd[512];
    __shared__ int s_carry;
    int tid = threadIdx.x;
    if (tid == 0) s_carry = 0;
    __syncthreads();
    for (int b0 = 0; b0 < nb; b0 += 512) {
        int i = b0 + tid;
        int v = (i < nb) ? g_bsum[i] : 0;
        sd[tid] = v;
        __syncthreads();
        for (int o = 1; o < 512; o <<= 1) {
            int tv = (tid >= o) ? sd[tid - o] : 0;
            __syncthreads();
            sd[tid] += tv;
            __syncthreads();
        }
        int c = s_carry;
        if (i < nb) g_boff[i] = c + sd[tid] - v;
        __syncthreads();
        if (tid == 511) s_carry = c + sd[511];
        __syncthreads();
    }
    if (tid == 0) g_rowptr16[ntot] = s_carry;
}

__global__ void k_scanC(int ntot) {
    int i = blockIdx.x * blockDim.x + threadIdx.x;
    if (i >= ntot) return;
    int rp = g_rowptr16[i] + g_boff[i >> 8];
    g_rowptr16[i] = rp;
    g_cursor16[i] = rp;
}

__global__ void k_scatter(const int* __restrict__ ei, const int* __restrict__ et, int e) {
    int i = blockIdx.x * blockDim.x + threadIdx.x;
    if (i >= e) return;
    int key = ei[e + i] * 16 + et[i];
    int pos = atomicAdd(&g_cursor16[key], 1);
    g_epack[pos] = ei[i];
}

template <int F, int STRIDE>
__global__ void k_qv(int l, int n) {
    int idx = blockIdx.x * blockDim.x + threadIdx.x;
    if (idx >= n * 16) return;
    int node = idx >> 4, r = idx & 15;
    float sq = 0.f, sk = 0.f;
    if (r < RREL) {
        const float* x = (F == 35) ? g_x0 : g_x;
        const float* wq = g_wq[l][r];
        const float* wk = g_wk[l][r];
        #pragma unroll
        for (int f = 0; f < F; f++) {
            float xv = x[(size_t)node * STRIDE + f];
            sq += xv * wq[f]; sk += xv * wk[f];
        }
    }
    g_qv[idx] = sq;
    g_kv[idx] = sk;
}

// Warp per dst: per-(dst,r) segments, register accumulator, gather from L2-hot g_x16.
template <int FP>
__global__ void k_edge(int n) {
    int warp = threadIdx.x >> 5, lane = threadIdx.x & 31;
    int node = blockIdx.x * 8 + warp;
    if (node >= n) return;
    __shared__ float sqv[8][16];
    if (lane < 16) sqv[warp][lane] = g_qv[node * 16 + lane];
    __syncwarp();
    int base = node * 16;
    // pass 1: exp-logits per relation segment + denominator
    float s = 0.f;
    for (int r = 0; r < RREL; r++) {
        int b = g_rowptr16[base + r], e2 = g_rowptr16[base + r + 1];
        float qvr = sqv[warp][r];
        for (int i = b + lane; i < e2; i += 32) {
            int src = g_epack[i];
            float a = qvr + g_kv[src * 16 + r];
            a = (a > 0.f) ? a : 0.2f * a;
            float ee = __expf(a);
            g_alpha[i] = ee;
            s += ee;
        }
    }
    s = warpSumF(s);
    float inv = __fdividef(1.f, s + 1e-16f);
    // pass 2: per-relation weighted x accumulation -> S
    __half* srow = &g_S[(size_t)node * 544];
    for (int r = 0; r < RREL; r++) {
        int b = g_rowptr16[base + r], e2 = g_rowptr16[base + r + 1];
        float acc = 0.f, acc2 = 0.f;
        for (int cb = b; cb < e2; cb += 32) {
            int i = cb + lane;
            float pj = 0.f;
            int src = 0;
            if (i < e2) { src = g_epack[i]; pj = g_alpha[i] * inv; }
            int cnt = min(32, e2 - cb);
            for (int j = 0; j < cnt; j++) {
                float pw = __shfl_sync(0xffffffffu, pj, j);
                int sc = __shfl_sync(0xffffffffu, src, j);
                const __half* xr = &g_x16[(size_t)sc * FP];
                acc += pw * __half2float(xr[lane]);
                if (FP == 36 && lane < 4) acc2 += pw * __half2float(xr[32 + lane]);
            }
        }
        srow[r * FP + lane] = __float2half(acc);
        if (FP == 36 && lane < 4) srow[r * FP + 32 + lane] = __float2half(acc2);
    }
    if (FP == 36 && lane < 4) srow[540 + lane] = __float2half(0.f);
}

// h = S @ Wcat + bias (+ residual), fused LN stats.
template <int KSTEPS>
__global__ void k_gemmS(const float* __restrict__ bias, int layer, int n, int lidx) {
    constexpr int KTOT = KSTEPS * 16;
    constexpr int NCH = KTOT / 32;
    __shared__ __half wtc[32][546];
    __shared__ __half sS[128][40];
    __shared__ float sb[32];
    __shared__ double sred[2][4];
    int tid = threadIdx.x, w = tid >> 5, lane = tid & 31, g = lane >> 2, t = lane & 3;
    int base = blockIdx.x * 128;
    const __half* wc = g_Wcat + (size_t)lidx * 544 * 32;
    for (int idx = tid; idx < 32 * KTOT; idx += 128) {
        int kk = idx >> 5, o = idx & 31;
        wtc[o][kk] = wc[kk * 32 + o];
    }
    if (tid < 32) sb[tid] = bias[tid];
    float d[2][4][4];
    #pragma unroll
    for (int a = 0; a < 2; a++)
        #pragma unroll
        for (int b = 0; b < 4; b++)
            #pragma unroll
            for (int c = 0; c < 4; c++) d[a][b][c] = 0.f;
    for (int ch = 0; ch < NCH; ch++) {
        __syncthreads();
        int cb = ch * 32;
        #pragma unroll
        for (int j = 0; j < 16; j++) {
            int wd = tid + 128 * j;
            int row = wd >> 4, cw = wd & 15;
            uint32_t v = 0;
            int node = base + row;
            if (node < n) v = *(const uint32_t*)&g_S[(size_t)node * 544 + cb + 2 * cw];
            *(uint32_t*)&sS[row][2 * cw] = v;
        }
        __syncthreads();
        #pragma unroll
        for (int ks = 0; ks < 2; ks++) {
            #pragma unroll
            for (int mt = 0; mt < 2; mt++) {
                int rb = w * 32 + mt * 16;
                uint32_t a0 = *(const uint32_t*)&sS[rb + g][2 * t + ks * 16];
                uint32_t a1 = *(const uint32_t*)&sS[rb + g + 8][2 * t + ks * 16];
                uint32_t a2 = *(const uint32_t*)&sS[rb + g][2 * t + 8 + ks * 16];
                uint32_t a3 = *(const uint32_t*)&sS[rb + g + 8][2 * t + 8 + ks * 16];
                #pragma unroll
                for (int nt = 0; nt < 4; nt++) {
                    uint32_t b0 = *(const uint32_t*)&wtc[nt * 8 + g][cb + 2 * t + ks * 16];
                    uint32_t b1 = *(const uint32_t*)&wtc[nt * 8 + g][cb + 2 * t + 8 + ks * 16];
                    mma16816(d[mt][nt][0], d[mt][nt][1], d[mt][nt][2], d[mt][nt][3],
                             a0, a1, a2, a3, b0, b1);
                }
            }
        }
    }
    __syncthreads();
    double dsum = 0.0, dss = 0.0;
    #pragma unroll
    for (int mt = 0; mt < 2; mt++) {
        int r0 = base + w * 32 + mt * 16 + g;
        int r1 = r0 + 8;
        #pragma unroll
        for (int nt = 0; nt < 4; nt++) {
            int col = nt * 8 + 2 * t;
            float b0f = sb[col], b1f = sb[col + 1];
            if (r0 < n) {
                float h0 = d[mt][nt][0] + b0f, h1 = d[mt][nt][1] + b1f;
                if (layer > 0) { float2 rr = *(const float2*)&g_x[(size_t)r0 * 32 + col]; h0 += rr.x; h1 += rr.y; }
                *(float2*)&g_h[(size_t)r0 * 32 + col] = make_float2(h0, h1);
                dsum += (double)h0 + (double)h1;
                dss += (double)h0 * h0 + (double)h1 * h1;
            }
            if (r1 < n) {
                float h0 = d[mt][nt][2] + b0f, h1 = d[mt][nt][3] + b1f;
                if (layer > 0) { float2 rr = *(const float2*)&g_x[(size_t)r1 * 32 + col]; h0 += rr.x; h1 += rr.y; }
                *(float2*)&g_h[(size_t)r1 * 32 + col] = make_float2(h0, h1);
                dsum += (double)h0 + (double)h1;
                dss += (double)h0 * h0 + (double)h1 * h1;
            }
        }
    }
    dsum = warpSumD(dsum); dss = warpSumD(dss);
    if (lane == 0) { sred[0][w] = dsum; sred[1][w] = dss; }
    __syncthreads();
    if (tid == 0) {
        double a = sred[0][0] + sred[0][1] + sred[0][2] + sred[0][3];
        double b = sred[1][0] + sred[1][1] + sred[1][2] + sred[1][3];
        atomicAdd(&g_stats[layer][0], a);
        atomicAdd(&g_stats[layer][1], b);
    }
}

__global__ void k_lnact(const float* __restrict__ lnw, const float* __restrict__ lnb,
                        int layer, int n, int dopool) {
    __shared__ float s_mu, s_std;
    if (threadIdx.x == 0) {
        double cnt = (double)n * 32.0;
        double mu = g_stats[layer][0] / cnt;
        double var = g_stats[layer][1] / cnt - mu * mu;
        if (var < 0.0) var = 0.0;
        s_mu = (float)mu;
        s_std = (float)sqrt(var) + 1e-5f;
    }
    __syncthreads();
    float mu = s_mu, stdpe = s_std;
    int f = threadIdx.x & 31;
    float w = lnw[f], b = lnb[f];
    double acc = 0.0;
    int total = n * 32;
    for (int i = blockIdx.x * blockDim.x + threadIdx.x; i < total; i += gridDim.x * blockDim.x) {
        float t = (g_h[i] - mu) / stdpe * w + b;
        float sig = 1.f / (1.f + __expf(-t));
        float xo = t * sig;
        g_x[i] = xo;
        g_x16[i] = __float2half(xo);
        acc += (double)xo;
    }
    if (dopool) {
        __shared__ double shd[8][32];
        int warp = threadIdx.x >> 5;
        shd[warp][f] = acc;
        __syncthreads();
        if (warp == 0) {
            double a = 0;
            for (int ww = 0; ww < 8; ww++) a += shd[ww][f];
            atomicAdd(&g_pool[f], a);
        }
    }
}

__global__ void k_final(const float* __restrict__ W, const float* __restrict__ b,
                        float* __restrict__ out, int n) {
    __shared__ float x3[32];
    if (threadIdx.x < 32) x3[threadIdx.x] = (float)(g_pool[threadIdx.x] / (double)n);
    __syncthreads();
    int j = threadIdx.x;
    if (j < 256) {
        float acc = b[j];
        #pragma unroll
        for (int o = 0; o < 32; o++) acc += x3[o] * W[j * 32 + o];
        float sig = 1.f / (1.f + expf(-acc));
        out[j] = acc * sig;
    }
}

extern "C" void kernel_launch(void* const* d_in, const int* in_sizes, int n_in,
                              void* d_out, int out_size) {
    const float* db1  = (const float*)d_in[0];
    const int*   ei   = (const int*)d_in[2];
    const int*   et   = (const int*)d_in[3];
    const float* W0   = (const float*)d_in[6];
    const float* q0   = (const float*)d_in[7];
    const float* k0   = (const float*)d_in[8];
    const float* b0   = (const float*)d_in[9];
    const float* Ws   = (const float*)d_in[10];
    const float* qs   = (const float*)d_in[11];
    const float* ks   = (const float*)d_in[12];
    const float* bs   = (const float*)d_in[13];
    const float* lnw  = (const float*)d_in[14];
    const float* lnb  = (const float*)d_in[15];
    const float* ln1w = (const float*)d_in[16];
    const float* ln1b = (const float*)d_in[17];
    const float* l1W  = (const float*)d_in[18];
    const float* l1b  = (const float*)d_in[19];
    float* out = (float*)d_out;
    int n = in_sizes[0] / 35;
    int e = in_sizes[3];
    int ntot = n * 16;
    int nb16 = (ntot + 255) / 256;

    k_wprep<<<(4 * 544 * 32 + 4 * RREL * 36 + 255) / 256, 256>>>(W0, q0, k0, Ws, qs, ks);
    k_zero<<<512, 256>>>();
    k_hist<<<(e + 255) / 256, 256>>>(ei, et, e);
    k_stats<<<512, 256>>>(db1, n);
    k_eigh<<<1, 1>>>(n);
    k_buildx0<<<(n * 36 + 255) / 256, 256>>>(db1, ln1w, ln1b, n);
    k_scanA<<<nb16, 256>>>(ntot);
    k_scanB<<<1, 512>>>(nb16, ntot);
    k_scanC<<<nb16, 256>>>(ntot);
    k_scatter<<<(e + 255) / 256, 256>>>(ei, et, e);

    int gg = (n + 127) / 128;
    for (int l = 0; l < NLAY; l++) {
        const float* bias = (l == 0) ? b0 : bs + (l - 1) * 32;
        if (l == 0) {
            k_qv<35, 36><<<(n * 16 + 255) / 256, 256>>>(l, n);
            k_edge<36><<<(n + 7) / 8, 256>>>(n);
            k_gemmS<34><<<gg, 128>>>(bias, l, n, l);
        } else {
            k_qv<32, 32><<<(n * 16 + 255) / 256, 256>>>(l, n);
            k_edge<32><<<(n + 7) / 8, 256>>>(n);
            k_gemmS<30><<<gg, 128>>>(bias, l, n, l);
        }
        k_lnact<<<512, 256>>>(lnw + l * 32, lnb + l * 32, l, n, (l == NLAY - 1) ? 1 : 0);
    }
    k_final<<<1, 256>>>(l1W, l1b, out, n);
}

// round 11
// speedup vs baseline: 1.4413x; 1.4413x over previous
#include <cuda_runtime.h>
#include <cuda_fp16.h>
#include <math.h>
#include <stdint.h>

#define NMAX 100000
#define EMAX 3200000
#define RREL 15
#define NLAY 4

__device__ __half g_xr[(size_t)RREL * NMAX * 32];
__device__ float g_x0[NMAX * 36];
__device__ float g_x[NMAX * 32];
__device__ float g_h[NMAX * 32];
__device__ float g_qv[NMAX * 16];
__device__ float g_kv[NMAX * 16];
__device__ int   g_rowptr[NMAX + 1];
__device__ int   g_cursor[NMAX];
__device__ int   g_count[NMAX];
__device__ int   g_epack[EMAX];
__device__ int   g_bsum[512];
__device__ int   g_boff[512];
__device__ double g_stats[NLAY][2];
__device__ double g_pool[32];
__device__ double g_psum[3];
__device__ double g_M[6];
__device__ unsigned int g_mnkey[3], g_mxkey[3];
__device__ float  g_pmean[3];
__device__ float g_V[9];
__device__ float g_pscale;
__device__ double g_fstats[2];
__device__ float  g_fp[2];

__device__ __forceinline__ double warpSumD(double v) {
    for (int o = 16; o > 0; o >>= 1) v += __shfl_down_sync(0xffffffffu, v, o);
    return v;
}
__device__ __forceinline__ float warpSumF(float v) {
    for (int o = 16; o > 0; o >>= 1) v += __shfl_xor_sync(0xffffffffu, v, o);
    return v;
}
__device__ __forceinline__ unsigned int fkey(float f) {
    unsigned int u = __float_as_uint(f);
    return (u & 0x80000000u) ? ~u : (u | 0x80000000u);
}
__device__ __forceinline__ float funkey(unsigned int k) {
    return (k & 0x80000000u) ? __uint_as_float(k ^ 0x80000000u) : __uint_as_float(~k);
}

__device__ __forceinline__ void mma16816(float& d0, float& d1, float& d2, float& d3,
    uint32_t a0, uint32_t a1, uint32_t a2, uint32_t a3, uint32_t b0, uint32_t b1) {
    asm volatile("mma.sync.aligned.m16n8k16.row.col.f32.f16.f16.f32 "
        "{%0,%1,%2,%3}, {%4,%5,%6,%7}, {%8,%9}, {%0,%1,%2,%3};"
        : "+f"(d0), "+f"(d1), "+f"(d2), "+f"(d3)
        : "r"(a0), "r"(a1), "r"(a2), "r"(a3), "r"(b0), "r"(b1));
}

__global__ void k_zero(int n) {
    int i = blockIdx.x * blockDim.x + threadIdx.x;
    for (int j = i; j < n; j += gridDim.x * blockDim.x) g_count[j] = 0;
    if (i == 0) {
        for (int l = 0; l < NLAY; l++) { g_stats[l][0] = 0.0; g_stats[l][1] = 0.0; }
        for (int o = 0; o < 32; o++) g_pool[o] = 0.0;
        for (int c = 0; c < 3; c++) { g_psum[c] = 0.0; g_mnkey[c] = 0xFFFFFFFFu; g_mxkey[c] = 0u; }
        for (int c = 0; c < 6; c++) g_M[c] = 0.0;
        g_fstats[0] = 0.0; g_fstats[1] = 0.0;
    }
}

// Fused stats: position moments (n-loop) + feature moments (flat float4 stream).
__global__ void k_stats(const float* __restrict__ d, int n) {
    int gtid = blockIdx.x * blockDim.x + threadIdx.x;
    int stride = gridDim.x * blockDim.x;
    double s0 = 0, s1 = 0, s2 = 0;
    double r00 = 0, r01 = 0, r02 = 0, r11 = 0, r12 = 0, r22 = 0;
    float mn0 = 3e38f, mn1 = 3e38f, mn2 = 3e38f;
    float mx0 = -3e38f, mx1 = -3e38f, mx2 = -3e38f;
    for (int i = gtid; i < n; i += stride) {
        float x = d[i * 35 + 0], y = d[i * 35 + 1], z = d[i * 35 + 2];
        double dx = x, dy = y, dz = z;
        s0 += dx; s1 += dy; s2 += dz;
        r00 += dx * dx; r01 += dx * dy; r02 += dx * dz;
        r11 += dy * dy; r12 += dy * dz; r22 += dz * dz;
        mn0 = fminf(mn0, x); mx0 = fmaxf(mx0, x);
        mn1 = fminf(mn1, y); mx1 = fmaxf(mx1, y);
        mn2 = fminf(mn2, z); mx2 = fmaxf(mx2, z);
    }
    // feature sums from flat coalesced stream, skipping position columns
    double fs = 0, fss = 0;
    int total = n * 35;
    int q4 = total >> 2;
    const float4* d4 = (const float4*)d;
    for (int j = gtid; j < q4; j += stride) {
        float4 v = d4[j];
        int idx = j * 4;
        int c = idx - (idx / 35) * 35;
        if (c >= 3) { double t = v.x; fs += t; fss += t * t; }
        c = (c == 34) ? 0 : c + 1;
        if (c >= 3) { double t = v.y; fs += t; fss += t * t; }
        c = (c == 34) ? 0 : c + 1;
        if (c >= 3) { double t = v.z; fs += t; fss += t * t; }
        c = (c == 34) ? 0 : c + 1;
        if (c >= 3) { double t = v.w; fs += t; fss += t * t; }
    }
    if (gtid == 0) {
        for (int idx = q4 * 4; idx < total; idx++) {
            int c = idx - (idx / 35) * 35;
            if (c >= 3) { double t = d[idx]; fs += t; fss += t * t; }
        }
    }
    s0 = warpSumD(s0); s1 = warpSumD(s1); s2 = warpSumD(s2);
    r00 = warpSumD(r00); r01 = warpSumD(r01); r02 = warpSumD(r02);
    r11 = warpSumD(r11); r12 = warpSumD(r12); r22 = warpSumD(r22);
    fs = warpSumD(fs); fss = warpSumD(fss);
    for (int o = 16; o > 0; o >>= 1) {
        mn0 = fminf(mn0, __shfl_down_sync(0xffffffffu, mn0, o));
        mn1 = fminf(mn1, __shfl_down_sync(0xffffffffu, mn1, o));
        mn2 = fminf(mn2, __shfl_down_sync(0xffffffffu, mn2, o));
        mx0 = fmaxf(mx0, __shfl_down_sync(0xffffffffu, mx0, o));
        mx1 = fmaxf(mx1, __shfl_down_sync(0xffffffffu, mx1, o));
        mx2 = fmaxf(mx2, __shfl_down_sync(0xffffffffu, mx2, o));
    }
    if ((threadIdx.x & 31) == 0) {
        atomicAdd(&g_psum[0], s0); atomicAdd(&g_psum[1], s1); atomicAdd(&g_psum[2], s2);
        atomicAdd(&g_M[0], r00); atomicAdd(&g_M[1], r01); atomicAdd(&g_M[2], r02);
        atomicAdd(&g_M[3], r11); atomicAdd(&g_M[4], r12); atomicAdd(&g_M[5], r22);
        atomicAdd(&g_fstats[0], fs); atomicAdd(&g_fstats[1], fss);
        atomicMin(&g_mnkey[0], fkey(mn0)); atomicMax(&g_mxkey[0], fkey(mx0));
        atomicMin(&g_mnkey[1], fkey(mn1)); atomicMax(&g_mxkey[1], fkey(mx1));
        atomicMin(&g_mnkey[2], fkey(mn2)); atomicMax(&g_mxkey[2], fkey(mx2));
    }
}

// ---- LAPACK dsyevd path (PASSING convention): dsytd2('L') -> dsteqr('I') -> V=Q*Z ----
__device__ void dev_dlartg(double f, double g, double* cs, double* sn, double* r) {
    if (g == 0.0) { *cs = 1.0; *sn = 0.0; *r = f; }
    else if (f == 0.0) { *cs = 0.0; *sn = 1.0; *r = g; }
    else {
        double rr = sqrt(f * f + g * g);
        double c = f / rr, s = g / rr;
        if (fabs(f) > fabs(g) && c < 0.0) { c = -c; s = -s; rr = -rr; }
        *cs = c; *sn = s; *r = rr;
    }
}

__device__ void dev_dlaev2(double a, double b, double c,
                           double* rt1, double* rt2, double* cs1, double* sn1) {
    double sm = a + c, df = a - c;
    double adf = fabs(df), tb = b + b, ab = fabs(tb);
    double acmx, acmn;
    if (fabs(a) > fabs(c)) { acmx = a; acmn = c; } else { acmx = c; acmn = a; }
    double rt;
    if (adf > ab) rt = adf * sqrt(1.0 + (ab / adf) * (ab / adf));
    else if (adf < ab) rt = ab * sqrt(1.0 + (adf / ab) * (adf / ab));
    else rt = ab * sqrt(2.0);
    int sgn1;
    if (sm < 0.0) { *rt1 = 0.5 * (sm - rt); sgn1 = -1; *rt2 = (acmx / *rt1) * acmn - (b / *rt1) * b; }
    else if (sm > 0.0) { *rt1 = 0.5 * (sm + rt); sgn1 = 1; *rt2 = (acmx / *rt1) * acmn - (b / *rt1) * b; }
    else { *rt1 = 0.5 * rt; *rt2 = -0.5 * rt; sgn1 = 1; }
    double cs; int sgn2;
    if (df >= 0.0) { cs = df + rt; sgn2 = 1; } else { cs = df - rt; sgn2 = -1; }
    double acs = fabs(cs);
    if (acs > ab) {
        double ct = -tb / cs;
        *sn1 = 1.0 / sqrt(1.0 + ct * ct);
        *cs1 = ct * (*sn1);
    } else {
        if (ab == 0.0) { *cs1 = 1.0; *sn1 = 0.0; }
        else {
            double tn = -cs / tb;
            *cs1 = 1.0 / sqrt(1.0 + tn * tn);
            *sn1 = tn * (*cs1);
        }
    }
    if (sgn1 == sgn2) { double tn = *cs1; *cs1 = -(*sn1); *sn1 = tn; }
}

__global__ void k_eigh(int nn) {
    if (threadIdx.x != 0) return;
    double mu0 = g_psum[0] / (double)nn, mu1 = g_psum[1] / (double)nn, mu2 = g_psum[2] / (double)nn;
    g_pmean[0] = (float)mu0; g_pmean[1] = (float)mu1; g_pmean[2] = (float)mu2;
    {
        double cnt = (double)nn * 32.0;
        double mu = g_fstats[0] / cnt;
        double var = g_fstats[1] / cnt - mu * mu;
        if (var < 0.0) var = 0.0;
        g_fp[0] = (float)mu;
        g_fp[1] = (float)sqrt(var) + 1e-5f;
    }
    double mus[3] = {mu0, mu1, mu2};
    float mxab = 0.f;
    for (int c = 0; c < 3; c++) {
        float hi = funkey(g_mxkey[c]) - (float)mus[c];
        float lo = (float)mus[c] - funkey(g_mnkey[c]);
        mxab = fmaxf(mxab, fmaxf(hi, lo));
    }
    float sc = (1.0f / mxab) * 0.999999f;
    g_pscale = sc;
    double s2 = (double)sc * (double)sc;
    double N = (double)nn;
    double a00 = (g_M[0] - N * mu0 * mu0) * s2;
    double a01 = (g_M[1] - N * mu0 * mu1) * s2;
    double a02 = (g_M[2] - N * mu0 * mu2) * s2;
    double a11 = (g_M[3] - N * mu1 * mu1) * s2;
    double a12 = (g_M[4] - N * mu1 * mu2) * s2;
    double a22 = (g_M[5] - N * mu2 * mu2) * s2;

    double d[4], e[3];
    double tau = 0.0, v1 = 0.0;
    {
        double alpha = a01;
        double x = a02;
        double xnorm = fabs(x);
        double beta;
        if (xnorm == 0.0) { tau = 0.0; beta = alpha; }
        else {
            double hy = sqrt(alpha * alpha + xnorm * xnorm);
            beta = (alpha >= 0.0) ? -hy : hy;
            tau = (beta - alpha) / beta;
            v1 = x / (alpha - beta);
        }
        e[1] = beta;
        double nd11 = a11, nd12 = a12, nd22 = a22;
        if (tau != 0.0) {
            double w0 = tau * (a11 + a12 * v1);
            double w1 = tau * (a12 + a22 * v1);
            double al = -0.5 * tau * (w0 + w1 * v1);
            w0 += al;
            w1 += al * v1;
            nd11 = a11 - 2.0 * w0;
            nd12 = a12 - (w1 + w0 * v1);
            nd22 = a22 - 2.0 * v1 * w1;
        }
        d[1] = a00; d[2] = nd11; d[3] = nd22;
        e[2] = nd12;
    }

    const int n = 3;
    double Z[4][4];
    for (int i = 1; i <= 3; i++)
        for (int j = 1; j <= 3; j++) Z[i][j] = (i == j) ? 1.0 : 0.0;
    double eps = 2.220446049250313e-16;
    double eps2 = eps * eps;
    double safmin = 2.2250738585072014e-308;
    int nmaxit = n * 30, jtot = 0;
    double wc[4], ws[4];
    int l1 = 1;
    while (true) {
        if (l1 > n) break;
        if (l1 > 1) e[l1 - 1] = 0.0;
        int m;
        if (l1 <= n - 1) {
            for (m = l1; m <= n - 1; m++) {
                double tst = fabs(e[m]);
                if (tst == 0.0) break;
                if (tst <= (sqrt(fabs(d[m])) * sqrt(fabs(d[m + 1]))) * eps) { e[m] = 0.0; break; }
            }
        } else m = n;
        int l = l1, lend = m;
        l1 = m + 1;
        if (lend == l) continue;
        if (fabs(d[lend]) < fabs(d[l])) { int t = lend; lend = l; l = t; }
        if (lend > l) {
            while (true) {
                int mm;
                if (l != lend) {
                    for (mm = l; mm <= lend - 1; mm++) {
                        double tst = e[mm] * e[mm];
                        if (tst <= (eps2 * fabs(d[mm]) * fabs(d[mm + 1]) + safmin)) break;
                    }
                } else mm = lend;
                m = mm;
                if (m < lend) e[m] = 0.0;
                double p = d[l];
                if (m == l) { d[l] = p; l = l + 1; if (l <= lend) continue; else break; }
                if (m == l + 1) {
                    double rt1, rt2, c, s;
                    dev_dlaev2(d[l], e[l], d[l + 1], &rt1, &rt2, &c, &s);
                    for (int i = 1; i <= n; i++) {
                        double temp = Z[i][l + 1];
                        Z[i][l + 1] = c * temp - s * Z[i][l];
                        Z[i][l] = s * temp + c * Z[i][l];
                    }
                    d[l] = rt1; d[l + 1] = rt2; e[l] = 0.0;
                    l = l + 2;
                    if (l <= lend) continue; else break;
                }
                if (jtot == nmaxit) break;
                jtot++;
                double g = (d[l + 1] - p) / (2.0 * e[l]);
                double r = sqrt(g * g + 1.0);
                double sg = (g >= 0.0) ? fabs(r) : -fabs(r);
                g = d[m] - p + e[l] / (g + sg);
                double s = 1.0, c = 1.0;
                p = 0.0;
                for (int i = m - 1; i >= l; i--) {
                    double f = s * e[i];
                    double b = c * e[i];
                    dev_dlartg(g, f, &c, &s, &r);
                    if (i != m - 1) e[i + 1] = r;
                    g = d[i + 1] - p;
                    r = (d[i] - g) * s + 2.0 * c * b;
                    p = s * r;
                    d[i + 1] = g + p;
                    g = c * r - b;
                    wc[i] = c; ws[i] = -s;
                }
                for (int j = m - 1; j >= l; j--) {
                    double cj = wc[j], sj = ws[j];
                    for (int i = 1; i <= n; i++) {
                        double temp = Z[i][j + 1];
                        Z[i][j + 1] = cj * temp - sj * Z[i][j];
                        Z[i][j] = sj * temp + cj * Z[i][j];
                    }
                }
                d[l] = d[l] - p;
                e[l] = g;
            }
        } else {
            while (true) {
                int mm;
                if (l != lend) {
                    for (mm = l; mm >= lend + 1; mm--) {
                        double tst = e[mm - 1] * e[mm - 1];
                        if (tst <= (eps2 * fabs(d[mm]) * fabs(d[mm - 1]) + safmin)) break;
                    }
                } else mm = lend;
                m = mm;
                if (m > lend) e[m - 1] = 0.0;
                double p = d[l];
                if (m == l) { d[l] = p; l = l - 1; if (l >= lend) continue; else break; }
                if (m == l - 1) {
                    double rt1, rt2, c, s;
                    dev_dlaev2(d[l - 1], e[l - 1], d[l], &rt1, &rt2, &c, &s);
                    for (int i = 1; i <= n; i++) {
                        double temp = Z[i][l];
                        Z[i][l] = c * temp - s * Z[i][l - 1];
                        Z[i][l - 1] = s * temp + c * Z[i][l - 1];
                    }
                    d[l - 1] = rt1; d[l] = rt2; e[l - 1] = 0.0;
                    l = l - 2;
                    if (l >= lend) continue; else break;
                }
                if (jtot == nmaxit) break;
                jtot++;
                double g = (d[l - 1] - p) / (2.0 * e[l - 1]);
                double r = sqrt(g * g + 1.0);
                double sg = (g >= 0.0) ? fabs(r) : -fabs(r);
                g = d[m] - p + e[l - 1] / (g + sg);
                double s = 1.0, c = 1.0;
                p = 0.0;
                for (int i = m; i <= l - 1; i++) {
                    double f = s * e[i];
                    double b = c * e[i];
                    dev_dlartg(g, f, &c, &s, &r);
                    if (i != m) e[i - 1] = r;
                    g = d[i] - p;
                    r = (d[i + 1] - g) * s + 2.0 * c * b;
                    p = s * r;
                    d[i] = g + p;
                    g = c * r - b;
                    wc[i] = c; ws[i] = s;
                }
                for (int j = m; j <= l - 1; j++) {
                    double cj = wc[j], sj = ws[j];
                    for (int i = 1; i <= n; i++) {
                        double temp = Z[i][j + 1];
                        Z[i][j + 1] = cj * temp - sj * Z[i][j];
                        Z[i][j] = sj * temp + cj * Z[i][j];
                    }
                }
                d[l] = d[l] - p;
                e[l - 1] = g;
            }
        }
    }
    for (int ii = 2; ii <= n; ii++) {
        int i = ii - 1, k = i;
        double p = d[i];
        for (int j = ii; j <= n; j++) if (d[j] < p) { k = j; p = d[j]; }
        if (k != i) {
            d[k] = d[i]; d[i] = p;
            for (int rr = 1; rr <= n; rr++) { double t = Z[rr][i]; Z[rr][i] = Z[rr][k]; Z[rr][k] = t; }
        }
    }
    double Q[4][4];
    Q[1][1] = 1.0; Q[1][2] = 0.0; Q[1][3] = 0.0;
    Q[2][1] = 0.0; Q[3][1] = 0.0;
    Q[2][2] = 1.0 - tau;
    Q[2][3] = -tau * v1;
    Q[3][2] = -tau * v1;
    Q[3][3] = 1.0 - tau * v1 * v1;
    for (int i = 1; i <= 3; i++)
        for (int j = 1; j <= 3; j++) {
            double acc = 0.0;
            for (int k = 1; k <= 3; k++) acc += Q[i][k] * Z[k][j];
            g_V[(i - 1) * 3 + (j - 1)] = (float)acc;
        }
}

__global__ void k_buildx0(const float* __restrict__ d, const float* __restrict__ ln1w,
                          const float* __restrict__ ln1b, int n) {
    int idx = blockIdx.x * blockDim.x + threadIdx.x;
    if (idx >= n * 36) return;
    int node = idx / 36, j = idx % 36;
    float val;
    if (j < 3) {
        float sc = g_pscale;
        float a = (d[node * 35 + 0] - g_pmean[0]) * sc;
        float b = (d[node * 35 + 1] - g_pmean[1]) * sc;
        float c = (d[node * 35 + 2] - g_pmean[2]) * sc;
        val = a * g_V[0 + j] + b * g_V[3 + j] + c * g_V[6 + j];
    } else if (j < 35) {
        val = (d[node * 35 + j] - g_fp[0]) / g_fp[1] * ln1w[j - 3] + ln1b[j - 3];
    } else val = 0.f;
    g_x0[idx] = val;
}

__global__ void k_hist(const int* __restrict__ ei, int e) {
    int i = blockIdx.x * blockDim.x + threadIdx.x;
    if (i < e) atomicAdd(&g_count[ei[e + i]], 1);
}

__global__ void k_scanA(int n) {
    __shared__ int ws[8];
    int b = blockIdx.x, tid = threadIdx.x, lane = tid & 31, w = tid >> 5;
    int i = b * 256 + tid;
    int v = (i < n) ? g_count[i] : 0;
    int x = v;
    for (int o = 1; o < 32; o <<= 1) {
        int y = __shfl_up_sync(0xffffffffu, x, o);
        if (lane >= o) x += y;
    }
    if (lane == 31) ws[w] = x;
    __syncthreads();
    if (tid == 0) {
        int run = 0;
        for (int j = 0; j < 8; j++) { int t = ws[j]; ws[j] = run; run += t; }
    }
    __syncthreads();
    int excl = x - v + ws[w];
    if (i < n) g_rowptr[i] = excl;
    if (tid == 255) g_bsum[b] = excl + v;
}

__global__ void k_scanB(int nb, int n) {
    __shared__ int sd[512];
    int tid = threadIdx.x;
    int v = (tid < nb) ? g_bsum[tid] : 0;
    sd[tid] = v;
    __syncthreads();
    for (int o = 1; o < 512; o <<= 1) {
        int t = (tid >= o) ? sd[tid - o] : 0;
        __syncthreads();
        sd[tid] += t;
        __syncthreads();
    }
    if (tid < nb) g_boff[tid] = sd[tid] - v;
    if (tid == nb - 1) g_rowptr[n] = sd[tid];
}

__global__ void k_scanC(int n) {
    int i = blockIdx.x * blockDim.x + threadIdx.x;
    if (i >= n) return;
    int rp = g_rowptr[i] + g_boff[i >> 8];
    g_rowptr[i] = rp;
    g_cursor[i] = rp;
}

__global__ void k_scatter(const int* __restrict__ ei, const int* __restrict__ et, int e) {
    int i = blockIdx.x * blockDim.x + threadIdx.x;
    if (i >= e) return;
    int pos = atomicAdd(&g_cursor[ei[e + i]], 1);
    g_epack[pos] = ei[i] | (et[i] << 20);
}

// Tensor-core GEMM: xr[r] = x @ W[r] (fp16 in, fp32 acc), qv/kv fused epilogue.
template <int F, int STRIDE, int KP>
__global__ void k_gemm(const float* __restrict__ W, const float* __restrict__ qvec,
                       const float* __restrict__ kvec, int n) {
    __shared__ __half xs[128][56];
    __shared__ __half wt[32][56];
    __shared__ __half xout[128][36];
    __shared__ float sq[32], sk[32];
    int tid = threadIdx.x;
    int w = tid >> 5, lane = tid & 31, g = lane >> 2, t = lane & 3;
    int base = blockIdx.x * 128;
    const float* xbuf = (F == 35) ? g_x0 : g_x;

    for (int idx = tid; idx < 128 * KP; idx += 128) {
        int nl = idx / KP, f = idx % KP;
        int node = base + nl;
        float v = (f < F && node < n) ? xbuf[(size_t)node * STRIDE + f] : 0.f;
        xs[nl][f] = __float2half(v);
    }
    if (tid < 32) { sq[tid] = qvec[tid]; sk[tid] = kvec[tid]; }

    for (int r = 0; r < RREL; r++) {
        __syncthreads();
        for (int idx = tid; idx < 32 * KP; idx += 128) {
            int o = idx / KP, f = idx % KP;
            wt[o][f] = (f < F) ? __float2half(W[((size_t)r * F + f) * 32 + o]) : __float2half(0.f);
        }
        __syncthreads();
        for (int mt = 0; mt < 2; mt++) {
            int rowbase = w * 32 + mt * 16;
            float qp0 = 0, qp1 = 0, kp0 = 0, kp1 = 0;
            for (int nt = 0; nt < 4; nt++) {
                float d0 = 0, d1 = 0, d2 = 0, d3 = 0;
                #pragma unroll
                for (int ks = 0; ks < KP / 16; ks++) {
                    uint32_t a0 = *(const uint32_t*)&xs[rowbase + g][2 * t + ks * 16];
                    uint32_t a1 = *(const uint32_t*)&xs[rowbase + g + 8][2 * t + ks * 16];
                    uint32_t a2 = *(const uint32_t*)&xs[rowbase + g][2 * t + 8 + ks * 16];
                    uint32_t a3 = *(const uint32_t*)&xs[rowbase + g + 8][2 * t + 8 + ks * 16];
                    uint32_t b0 = *(const uint32_t*)&wt[nt * 8 + g][2 * t + ks * 16];
                    uint32_t b1 = *(const uint32_t*)&wt[nt * 8 + g][2 * t + 8 + ks * 16];
                    mma16816(d0, d1, d2, d3, a0, a1, a2, a3, b0, b1);
                }
                int c = nt * 8 + 2 * t;
                *(__half2*)&xout[rowbase + g][c] = __floats2half2_rn(d0, d1);
                *(__half2*)&xout[rowbase + g + 8][c] = __floats2half2_rn(d2, d3);
                qp0 += d0 * sq[c] + d1 * sq[c + 1];
                qp1 += d2 * sq[c] + d3 * sq[c + 1];
                kp0 += d0 * sk[c] + d1 * sk[c + 1];
                kp1 += d2 * sk[c] + d3 * sk[c + 1];
            }
            qp0 += __shfl_xor_sync(0xffffffffu, qp0, 1); qp0 += __shfl_xor_sync(0xffffffffu, qp0, 2);
            qp1 += __shfl_xor_sync(0xffffffffu, qp1, 1); qp1 += __shfl_xor_sync(0xffffffffu, qp1, 2);
            kp0 += __shfl_xor_sync(0xffffffffu, kp0, 1); kp0 += __shfl_xor_sync(0xffffffffu, kp0, 2);
            kp1 += __shfl_xor_sync(0xffffffffu, kp1, 1); kp1 += __shfl_xor_sync(0xffffffffu, kp1, 2);
            if (t == 0) {
                int n0 = base + rowbase + g, n1 = n0 + 8;
                if (n0 < n) { g_qv[n0 * 16 + r] = qp0; g_kv[n0 * 16 + r] = kp0; }
                if (n1 < n) { g_qv[n1 * 16 + r] = qp1; g_kv[n1 * 16 + r] = kp1; }
            }
        }
        __syncwarp();
        #pragma unroll
        for (int i = 0; i < 16; i++) {
            int rl = w * 32 + 2 * i + (lane >> 4);
            int node = base + rl;
            if (node < n) {
                uint32_t v = *(const uint32_t*)&xout[rl][(lane & 15) * 2];
                *(uint32_t*)&g_xr[((size_t)r * n + node) * 32 + (lane & 15) * 2] = v;
            }
        }
    }
}

// ONE-PASS edge kernel: deferred softmax normalization, fused logit+gather.
__global__ void k_edge(const float* __restrict__ bias, int layer, int n) {
    int warp = threadIdx.x >> 5, lane = threadIdx.x & 31;
    int node = blockIdx.x * 8 + warp;
    float h = 0.f;
    bool active = node < n;
    __shared__ float sh_qv[8][16];
    __shared__ float sh_h[8][32];
    if (active && lane < 16) sh_qv[warp][lane] = g_qv[node * 16 + lane];
    __syncwarp();
    if (active) {
        int beg = g_rowptr[node], end = g_rowptr[node + 1];
        float res = (layer > 0) ? g_x[(size_t)node * 32 + lane] : 0.f;
        if (end > beg) {
            int fq = lane & 3, eg = lane >> 2;
            float s = 0.f;
            float acc[8];
            #pragma unroll
            for (int j = 0; j < 8; j++) acc[j] = 0.f;
            for (int cb = beg; cb < end; cb += 32) {
                int i = cb + lane;
                float ee = 0.f;
                int ofs = 0;
                if (i < end) {
                    int p = g_epack[i];
                    int r = p >> 20, src = p & 0xFFFFF;
                    float a = sh_qv[warp][r] + g_kv[src * 16 + r];
                    a = (a > 0.f) ? a : 0.2f * a;
                    ee = __expf(a);
                    ofs = (r * n + src) * 32;
                }
                s += ee;
                int cnt = min(32, end - cb);
                for (int jb = 0; jb < cnt; jb += 8) {
                    int sl = jb + eg;
                    float pw = __shfl_sync(0xffffffffu, ee, sl & 31);
                    int of = __shfl_sync(0xffffffffu, ofs, sl & 31);
                    if (sl >= cnt) pw = 0.f;
                    uint4 v = *(const uint4*)&g_xr[(size_t)of + fq * 8];
                    float2 f0 = __half22float2(*(__half2*)&v.x);
                    float2 f1 = __half22float2(*(__half2*)&v.y);
                    float2 f2 = __half22float2(*(__half2*)&v.z);
                    float2 f3 = __half22float2(*(__half2*)&v.w);
                    acc[0] += pw * f0.x; acc[1] += pw * f0.y;
                    acc[2] += pw * f1.x; acc[3] += pw * f1.y;
                    acc[4] += pw * f2.x; acc[5] += pw * f2.y;
                    acc[6] += pw * f3.x; acc[7] += pw * f3.y;
                }
            }
            s = warpSumF(s);
            float inv = __fdividef(1.f, s + 1e-16f);
            #pragma unroll
            for (int j = 0; j < 8; j++) {
                acc[j] += __shfl_xor_sync(0xffffffffu, acc[j], 4);
                acc[j] += __shfl_xor_sync(0xffffffffu, acc[j], 8);
                acc[j] += __shfl_xor_sync(0xffffffffu, acc[j], 16);
            }
            if (eg == 0) {
                #pragma unroll
                for (int j = 0; j < 8; j++) sh_h[warp][fq * 8 + j] = acc[j] * inv;
            }
            __syncwarp();
            h = sh_h[warp][lane];
        }
        h += bias[lane] + res;
        g_h[(size_t)node * 32 + lane] = h;
    }
    double v = active ? (double)h : 0.0;
    double v2 = active ? (double)h * (double)h : 0.0;
    v = warpSumD(v); v2 = warpSumD(v2);
    __shared__ double sh[2][8];
    if (lane == 0) { sh[0][warp] = v; sh[1][warp] = v2; }
    __syncthreads();
    if (threadIdx.x == 0) {
        double a = 0, b = 0;
        for (int ww = 0; ww < 8; ww++) { a += sh[0][ww]; b += sh[1][ww]; }
        atomicAdd(&g_stats[layer][0], a);
        atomicAdd(&g_stats[layer][1], b);
    }
}

__global__ void k_lnact(const float* __restrict__ lnw, const float* __restrict__ lnb,
                        int layer, int n, int dopool) {
    __shared__ float s_mu, s_std;
    if (threadIdx.x == 0) {
        double cnt = (double)n * 32.0;
        double mu = g_stats[layer][0] / cnt;
        double var = g_stats[layer][1] / cnt - mu * mu;
        if (var < 0.0) var = 0.0;
        s_mu = (float)mu;
        s_std = (float)sqrt(var) + 1e-5f;
    }
    __syncthreads();
    float mu = s_mu, stdpe = s_std;
    int f = threadIdx.x & 31;
    float w = lnw[f], b = lnb[f];
    double acc = 0.0;
    int total = n * 32;
    for (int i = blockIdx.x * blockDim.x + threadIdx.x; i < total; i += gridDim.x * blockDim.x) {
        float t = (g_h[i] - mu) / stdpe * w + b;
        float sig = 1.f / (1.f + __expf(-t));
        float xo = t * sig;
        g_x[i] = xo;
        acc += (double)xo;
    }
    if (dopool) {
        __shared__ double shd[8][32];
        int warp = threadIdx.x >> 5;
        shd[warp][f] = acc;
        __syncthreads();
        if (warp == 0) {
            double a = 0;
            for (int ww = 0; ww < 8; ww++) a += shd[ww][f];
            atomicAdd(&g_pool[f], a);
        }
    }
}

__global__ void k_final(const float* __restrict__ W, const float* __restrict__ b,
                        float* __restrict__ out, int n) {
    __shared__ float x3[32];
    if (threadIdx.x < 32) x3[threadIdx.x] = (float)(g_pool[threadIdx.x] / (double)n);
    __syncthreads();
    int j = threadIdx.x;
    if (j < 256) {
        float acc = b[j];
        #pragma unroll
        for (int o = 0; o < 32; o++) acc += x3[o] * W[j * 32 + o];
        float sig = 1.f / (1.f + expf(-acc));
        out[j] = acc * sig;
    }
}

extern "C" void kernel_launch(void* const* d_in, const int* in_sizes, int n_in,
                              void* d_out, int out_size) {
    const float* db1  = (const float*)d_in[0];
    const int*   ei   = (const int*)d_in[2];
    const int*   et   = (const int*)d_in[3];
    const float* W0   = (const float*)d_in[6];
    const float* q0   = (const float*)d_in[7];
    const float* k0   = (const float*)d_in[8];
    const float* b0   = (const float*)d_in[9];
    const float* Ws   = (const float*)d_in[10];
    const float* qs   = (const float*)d_in[11];
    const float* ks   = (const float*)d_in[12];
    const float* bs   = (const float*)d_in[13];
    const float* lnw  = (const float*)d_in[14];
    const float* lnb  = (const float*)d_in[15];
    const float* ln1w = (const float*)d_in[16];
    const float* ln1b = (const float*)d_in[17];
    const float* l1W  = (const float*)d_in[18];
    const float* l1b  = (const float*)d_in[19];
    float* out = (float*)d_out;
    int n = in_sizes[0] / 35;
    int e = in_sizes[3];
    int nb = (n + 255) / 256;

    k_zero<<<nb, 256>>>(n);
    k_stats<<<512, 256>>>(db1, n);
    k_eigh<<<1, 1>>>(n);
    k_buildx0<<<(n * 36 + 255) / 256, 256>>>(db1, ln1w, ln1b, n);

    k_hist<<<(e + 255) / 256, 256>>>(ei, e);
    k_scanA<<<nb, 256>>>(n);
    k_scanB<<<1, 512>>>(nb, n);
    k_scanC<<<nb, 256>>>(n);
    k_scatter<<<(e + 255) / 256, 256>>>(ei, et, e);

    int gg = (n + 127) / 128;
    for (int l = 0; l < NLAY; l++) {
        const float* bias = (l == 0) ? b0 : bs + (l - 1) * 32;
        if (l == 0) {
            k_gemm<35, 36, 48><<<gg, 128>>>(W0, q0, k0, n);
        } else {
            k_gemm<32, 32, 32><<<gg, 128>>>(Ws + (size_t)(l - 1) * RREL * 32 * 32,
                                            qs + (l - 1) * 32, ks + (l - 1) * 32, n);
        }
        k_edge<<<(n + 7) / 8, 256>>>(bias, l, n);
        k_lnact<<<512, 256>>>(lnw + l * 32, lnb + l * 32, l, n, (l == NLAY - 1) ? 1 : 0);
    }
    k_final<<<1, 256>>>(l1W, l1b, out, n);
}

// round 12
// speedup vs baseline: 1.4445x; 1.0022x over previous
#include <cuda_runtime.h>
#include <cuda_fp16.h>
#include <math.h>
#include <stdint.h>

#define NMAX 100000
#define EMAX 3200000
#define RREL 15
#define NLAY 4
#define NB16 (NMAX * 16)

__device__ __half g_xr[(size_t)RREL * NMAX * 32];
__device__ float g_x0[NMAX * 36];
__device__ float g_x[NMAX * 32];
__device__ float g_h[NMAX * 32];
__device__ float g_qv[NMAX * 16];
__device__ float g_kv[NMAX * 16];
__device__ int   g_rowptr[NMAX + 1];
__device__ int   g_cursor16[NB16];
__device__ int   g_count16[NB16];
__device__ int   g_rp16[NB16];
__device__ int   g_epack[EMAX];
__device__ int   g_bsum[6400];
__device__ int   g_boff[6400];
__device__ double g_stats[NLAY][2];
__device__ double g_pool[32];
__device__ double g_psum[3];
__device__ double g_M[6];
__device__ unsigned int g_mnkey[3], g_mxkey[3];
__device__ float  g_pmean[3];
__device__ float g_V[9];
__device__ float g_pscale;
__device__ double g_fstats[2];
__device__ float  g_fp[2];

__device__ __forceinline__ double warpSumD(double v) {
    for (int o = 16; o > 0; o >>= 1) v += __shfl_down_sync(0xffffffffu, v, o);
    return v;
}
__device__ __forceinline__ float warpSumF(float v) {
    for (int o = 16; o > 0; o >>= 1) v += __shfl_xor_sync(0xffffffffu, v, o);
    return v;
}
__device__ __forceinline__ unsigned int fkey(float f) {
    unsigned int u = __float_as_uint(f);
    return (u & 0x80000000u) ? ~u : (u | 0x80000000u);
}
__device__ __forceinline__ float funkey(unsigned int k) {
    return (k & 0x80000000u) ? __uint_as_float(k ^ 0x80000000u) : __uint_as_float(~k);
}

__device__ __forceinline__ void mma16816(float& d0, float& d1, float& d2, float& d3,
    uint32_t a0, uint32_t a1, uint32_t a2, uint32_t a3, uint32_t b0, uint32_t b1) {
    asm volatile("mma.sync.aligned.m16n8k16.row.col.f32.f16.f16.f32 "
        "{%0,%1,%2,%3}, {%4,%5,%6,%7}, {%8,%9}, {%0,%1,%2,%3};"
        : "+f"(d0), "+f"(d1), "+f"(d2), "+f"(d3)
        : "r"(a0), "r"(a1), "r"(a2), "r"(a3), "r"(b0), "r"(b1));
}

__global__ void k_zero() {
    int i = blockIdx.x * blockDim.x + threadIdx.x;
    int stride = gridDim.x * blockDim.x;
    for (int j = i; j < NB16; j += stride) g_count16[j] = 0;
    if (i == 0) {
        for (int l = 0; l < NLAY; l++) { g_stats[l][0] = 0.0; g_stats[l][1] = 0.0; }
        for (int o = 0; o < 32; o++) g_pool[o] = 0.0;
        for (int c = 0; c < 3; c++) { g_psum[c] = 0.0; g_mnkey[c] = 0xFFFFFFFFu; g_mxkey[c] = 0u; }
        for (int c = 0; c < 6; c++) g_M[c] = 0.0;
        g_fstats[0] = 0.0; g_fstats[1] = 0.0;
    }
}

// Fused stats: position moments (n-loop) + feature moments (flat float4 stream).
__global__ void k_stats(const float* __restrict__ d, int n) {
    int gtid = blockIdx.x * blockDim.x + threadIdx.x;
    int stride = gridDim.x * blockDim.x;
    double s0 = 0, s1 = 0, s2 = 0;
    double r00 = 0, r01 = 0, r02 = 0, r11 = 0, r12 = 0, r22 = 0;
    float mn0 = 3e38f, mn1 = 3e38f, mn2 = 3e38f;
    float mx0 = -3e38f, mx1 = -3e38f, mx2 = -3e38f;
    for (int i = gtid; i < n; i += stride) {
        float x = d[i * 35 + 0], y = d[i * 35 + 1], z = d[i * 35 + 2];
        double dx = x, dy = y, dz = z;
        s0 += dx; s1 += dy; s2 += dz;
        r00 += dx * dx; r01 += dx * dy; r02 += dx * dz;
        r11 += dy * dy; r12 += dy * dz; r22 += dz * dz;
        mn0 = fminf(mn0, x); mx0 = fmaxf(mx0, x);
        mn1 = fminf(mn1, y); mx1 = fmaxf(mx1, y);
        mn2 = fminf(mn2, z); mx2 = fmaxf(mx2, z);
    }
    double fs = 0, fss = 0;
    int total = n * 35;
    int q4 = total >> 2;
    const float4* d4 = (const float4*)d;
    for (int j = gtid; j < q4; j += stride) {
        float4 v = d4[j];
        int idx = j * 4;
        int c = idx - (idx / 35) * 35;
        if (c >= 3) { double t = v.x; fs += t; fss += t * t; }
        c = (c == 34) ? 0 : c + 1;
        if (c >= 3) { double t = v.y; fs += t; fss += t * t; }
        c = (c == 34) ? 0 : c + 1;
        if (c >= 3) { double t = v.z; fs += t; fss += t * t; }
        c = (c == 34) ? 0 : c + 1;
        if (c >= 3) { double t = v.w; fs += t; fss += t * t; }
    }
    if (gtid == 0) {
        for (int idx = q4 * 4; idx < total; idx++) {
            int c = idx - (idx / 35) * 35;
            if (c >= 3) { double t = d[idx]; fs += t; fss += t * t; }
        }
    }
    s0 = warpSumD(s0); s1 = warpSumD(s1); s2 = warpSumD(s2);
    r00 = warpSumD(r00); r01 = warpSumD(r01); r02 = warpSumD(r02);
    r11 = warpSumD(r11); r12 = warpSumD(r12); r22 = warpSumD(r22);
    fs = warpSumD(fs); fss = warpSumD(fss);
    for (int o = 16; o > 0; o >>= 1) {
        mn0 = fminf(mn0, __shfl_down_sync(0xffffffffu, mn0, o));
        mn1 = fminf(mn1, __shfl_down_sync(0xffffffffu, mn1, o));
        mn2 = fminf(mn2, __shfl_down_sync(0xffffffffu, mn2, o));
        mx0 = fmaxf(mx0, __shfl_down_sync(0xffffffffu, mx0, o));
        mx1 = fmaxf(mx1, __shfl_down_sync(0xffffffffu, mx1, o));
        mx2 = fmaxf(mx2, __shfl_down_sync(0xffffffffu, mx2, o));
    }
    if ((threadIdx.x & 31) == 0) {
        atomicAdd(&g_psum[0], s0); atomicAdd(&g_psum[1], s1); atomicAdd(&g_psum[2], s2);
        atomicAdd(&g_M[0], r00); atomicAdd(&g_M[1], r01); atomicAdd(&g_M[2], r02);
        atomicAdd(&g_M[3], r11); atomicAdd(&g_M[4], r12); atomicAdd(&g_M[5], r22);
        atomicAdd(&g_fstats[0], fs); atomicAdd(&g_fstats[1], fss);
        atomicMin(&g_mnkey[0], fkey(mn0)); atomicMax(&g_mxkey[0], fkey(mx0));
        atomicMin(&g_mnkey[1], fkey(mn1)); atomicMax(&g_mxkey[1], fkey(mx1));
        atomicMin(&g_mnkey[2], fkey(mn2)); atomicMax(&g_mxkey[2], fkey(mx2));
    }
}

// ---- LAPACK dsyevd path (PASSING convention): dsytd2('L') -> dsteqr('I') -> V=Q*Z ----
__device__ void dev_dlartg(double f, double g, double* cs, double* sn, double* r) {
    if (g == 0.0) { *cs = 1.0; *sn = 0.0; *r = f; }
    else if (f == 0.0) { *cs = 0.0; *sn = 1.0; *r = g; }
    else {
        double rr = sqrt(f * f + g * g);
        double c = f / rr, s = g / rr;
        if (fabs(f) > fabs(g) && c < 0.0) { c = -c; s = -s; rr = -rr; }
        *cs = c; *sn = s; *r = rr;
    }
}

__device__ void dev_dlaev2(double a, double b, double c,
                           double* rt1, double* rt2, double* cs1, double* sn1) {
    double sm = a + c, df = a - c;
    double adf = fabs(df), tb = b + b, ab = fabs(tb);
    double acmx, acmn;
    if (fabs(a) > fabs(c)) { acmx = a; acmn = c; } else { acmx = c; acmn = a; }
    double rt;
    if (adf > ab) rt = adf * sqrt(1.0 + (ab / adf) * (ab / adf));
    else if (adf < ab) rt = ab * sqrt(1.0 + (adf / ab) * (adf / ab));
    else rt = ab * sqrt(2.0);
    int sgn1;
    if (sm < 0.0) { *rt1 = 0.5 * (sm - rt); sgn1 = -1; *rt2 = (acmx / *rt1) * acmn - (b / *rt1) * b; }
    else if (sm > 0.0) { *rt1 = 0.5 * (sm + rt); sgn1 = 1; *rt2 = (acmx / *rt1) * acmn - (b / *rt1) * b; }
    else { *rt1 = 0.5 * rt; *rt2 = -0.5 * rt; sgn1 = 1; }
    double cs; int sgn2;
    if (df >= 0.0) { cs = df + rt; sgn2 = 1; } else { cs = df - rt; sgn2 = -1; }
    double acs = fabs(cs);
    if (acs > ab) {
        double ct = -tb / cs;
        *sn1 = 1.0 / sqrt(1.0 + ct * ct);
        *cs1 = ct * (*sn1);
    } else {
        if (ab == 0.0) { *cs1 = 1.0; *sn1 = 0.0; }
        else {
            double tn = -cs / tb;
            *cs1 = 1.0 / sqrt(1.0 + tn * tn);
            *sn1 = tn * (*cs1);
        }
    }
    if (sgn1 == sgn2) { double tn = *cs1; *cs1 = -(*sn1); *sn1 = tn; }
}

__global__ void k_eigh(int nn) {
    if (threadIdx.x != 0) return;
    double mu0 = g_psum[0] / (double)nn, mu1 = g_psum[1] / (double)nn, mu2 = g_psum[2] / (double)nn;
    g_pmean[0] = (float)mu0; g_pmean[1] = (float)mu1; g_pmean[2] = (float)mu2;
    {
        double cnt = (double)nn * 32.0;
        double mu = g_fstats[0] / cnt;
        double var = g_fstats[1] / cnt - mu * mu;
        if (var < 0.0) var = 0.0;
        g_fp[0] = (float)mu;
        g_fp[1] = (float)sqrt(var) + 1e-5f;
    }
    double mus[3] = {mu0, mu1, mu2};
    float mxab = 0.f;
    for (int c = 0; c < 3; c++) {
        float hi = funkey(g_mxkey[c]) - (float)mus[c];
        float lo = (float)mus[c] - funkey(g_mnkey[c]);
        mxab = fmaxf(mxab, fmaxf(hi, lo));
    }
    float sc = (1.0f / mxab) * 0.999999f;
    g_pscale = sc;
    double s2 = (double)sc * (double)sc;
    double N = (double)nn;
    double a00 = (g_M[0] - N * mu0 * mu0) * s2;
    double a01 = (g_M[1] - N * mu0 * mu1) * s2;
    double a02 = (g_M[2] - N * mu0 * mu2) * s2;
    double a11 = (g_M[3] - N * mu1 * mu1) * s2;
    double a12 = (g_M[4] - N * mu1 * mu2) * s2;
    double a22 = (g_M[5] - N * mu2 * mu2) * s2;

    double d[4], e[3];
    double tau = 0.0, v1 = 0.0;
    {
        double alpha = a01;
        double x = a02;
        double xnorm = fabs(x);
        double beta;
        if (xnorm == 0.0) { tau = 0.0; beta = alpha; }
        else {
            double hy = sqrt(alpha * alpha + xnorm * xnorm);
            beta = (alpha >= 0.0) ? -hy : hy;
            tau = (beta - alpha) / beta;
            v1 = x / (alpha - beta);
        }
        e[1] = beta;
        double nd11 = a11, nd12 = a12, nd22 = a22;
        if (tau != 0.0) {
            double w0 = tau * (a11 + a12 * v1);
            double w1 = tau * (a12 + a22 * v1);
            double al = -0.5 * tau * (w0 + w1 * v1);
            w0 += al;
            w1 += al * v1;
            nd11 = a11 - 2.0 * w0;
            nd12 = a12 - (w1 + w0 * v1);
            nd22 = a22 - 2.0 * v1 * w1;
        }
        d[1] = a00; d[2] = nd11; d[3] = nd22;
        e[2] = nd12;
    }

    const int n = 3;
    double Z[4][4];
    for (int i = 1; i <= 3; i++)
        for (int j = 1; j <= 3; j++) Z[i][j] = (i == j) ? 1.0 : 0.0;
    double eps = 2.220446049250313e-16;
    double eps2 = eps * eps;
    double safmin = 2.2250738585072014e-308;
    int nmaxit = n * 30, jtot = 0;
    double wc[4], ws[4];
    int l1 = 1;
    while (true) {
        if (l1 > n) break;
        if (l1 > 1) e[l1 - 1] = 0.0;
        int m;
        if (l1 <= n - 1) {
            for (m = l1; m <= n - 1; m++) {
                double tst = fabs(e[m]);
                if (tst == 0.0) break;
                if (tst <= (sqrt(fabs(d[m])) * sqrt(fabs(d[m + 1]))) * eps) { e[m] = 0.0; break; }
            }
        } else m = n;
        int l = l1, lend = m;
        l1 = m + 1;
        if (lend == l) continue;
        if (fabs(d[lend]) < fabs(d[l])) { int t = lend; lend = l; l = t; }
        if (lend > l) {
            while (true) {
                int mm;
                if (l != lend) {
                    for (mm = l; mm <= lend - 1; mm++) {
                        double tst = e[mm] * e[mm];
                        if (tst <= (eps2 * fabs(d[mm]) * fabs(d[mm + 1]) + safmin)) break;
                    }
                } else mm = lend;
                m = mm;
                if (m < lend) e[m] = 0.0;
                double p = d[l];
                if (m == l) { d[l] = p; l = l + 1; if (l <= lend) continue; else break; }
                if (m == l + 1) {
                    double rt1, rt2, c, s;
                    dev_dlaev2(d[l], e[l], d[l + 1], &rt1, &rt2, &c, &s);
                    for (int i = 1; i <= n; i++) {
                        double temp = Z[i][l + 1];
                        Z[i][l + 1] = c * temp - s * Z[i][l];
                        Z[i][l] = s * temp + c * Z[i][l];
                    }
                    d[l] = rt1; d[l + 1] = rt2; e[l] = 0.0;
                    l = l + 2;
                    if (l <= lend) continue; else break;
                }
                if (jtot == nmaxit) break;
                jtot++;
                double g = (d[l + 1] - p) / (2.0 * e[l]);
                double r = sqrt(g * g + 1.0);
                double sg = (g >= 0.0) ? fabs(r) : -fabs(r);
                g = d[m] - p + e[l] / (g + sg);
                double s = 1.0, c = 1.0;
                p = 0.0;
                for (int i = m - 1; i >= l; i--) {
                    double f = s * e[i];
                    double b = c * e[i];
                    dev_dlartg(g, f, &c, &s, &r);
                    if (i != m - 1) e[i + 1] = r;
                    g = d[i + 1] - p;
                    r = (d[i] - g) * s + 2.0 * c * b;
                    p = s * r;
                    d[i + 1] = g + p;
                    g = c * r - b;
                    wc[i] = c; ws[i] = -s;
                }
                for (int j = m - 1; j >= l; j--) {
                    double cj = wc[j], sj = ws[j];
                    for (int i = 1; i <= n; i++) {
                        double temp = Z[i][j + 1];
                        Z[i][j + 1] = cj * temp - sj * Z[i][j];
                        Z[i][j] = sj * temp + cj * Z[i][j];
                    }
                }
                d[l] = d[l] - p;
                e[l] = g;
            }
        } else {
            while (true) {
                int mm;
                if (l != lend) {
                    for (mm = l; mm >= lend + 1; mm--) {
                        double tst = e[mm - 1] * e[mm - 1];
                        if (tst <= (eps2 * fabs(d[mm]) * fabs(d[mm - 1]) + safmin)) break;
                    }
                } else mm = lend;
                m = mm;
                if (m > lend) e[m - 1] = 0.0;
                double p = d[l];
                if (m == l) { d[l] = p; l = l - 1; if (l >= lend) continue; else break; }
                if (m == l - 1) {
                    double rt1, rt2, c, s;
                    dev_dlaev2(d[l - 1], e[l - 1], d[l], &rt1, &rt2, &c, &s);
                    for (int i = 1; i <= n; i++) {
                        double temp = Z[i][l];
                        Z[i][l] = c * temp - s * Z[i][l - 1];
                        Z[i][l - 1] = s * temp + c * Z[i][l - 1];
                    }
                    d[l - 1] = rt1; d[l] = rt2; e[l - 1] = 0.0;
                    l = l - 2;
                    if (l >= lend) continue; else break;
                }
                if (jtot == nmaxit) break;
                jtot++;
                double g = (d[l - 1] - p) / (2.0 * e[l - 1]);
                double r = sqrt(g * g + 1.0);
                double sg = (g >= 0.0) ? fabs(r) : -fabs(r);
                g = d[m] - p + e[l - 1] / (g + sg);
                double s = 1.0, c = 1.0;
                p = 0.0;
                for (int i = m; i <= l - 1; i++) {
                    double f = s * e[i];
                    double b = c * e[i];
                    dev_dlartg(g, f, &c, &s, &r);
                    if (i != m) e[i - 1] = r;
                    g = d[i] - p;
                    r = (d[i + 1] - g) * s + 2.0 * c * b;
                    p = s * r;
                    d[i] = g + p;
                    g = c * r - b;
                    wc[i] = c; ws[i] = s;
                }
                for (int j = m; j <= l - 1; j++) {
                    double cj = wc[j], sj = ws[j];
                    for (int i = 1; i <= n; i++) {
                        double temp = Z[i][j + 1];
                        Z[i][j + 1] = cj * temp - sj * Z[i][j];
                        Z[i][j] = sj * temp + cj * Z[i][j];
                    }
                }
                d[l] = d[l] - p;
                e[l - 1] = g;
            }
        }
    }
    for (int ii = 2; ii <= n; ii++) {
        int i = ii - 1, k = i;
        double p = d[i];
        for (int j = ii; j <= n; j++) if (d[j] < p) { k = j; p = d[j]; }
        if (k != i) {
            d[k] = d[i]; d[i] = p;
            for (int rr = 1; rr <= n; rr++) { double t = Z[rr][i]; Z[rr][i] = Z[rr][k]; Z[rr][k] = t; }
        }
    }
    double Q[4][4];
    Q[1][1] = 1.0; Q[1][2] = 0.0; Q[1][3] = 0.0;
    Q[2][1] = 0.0; Q[3][1] = 0.0;
    Q[2][2] = 1.0 - tau;
    Q[2][3] = -tau * v1;
    Q[3][2] = -tau * v1;
    Q[3][3] = 1.0 - tau * v1 * v1;
    for (int i = 1; i <= 3; i++)
        for (int j = 1; j <= 3; j++) {
            double acc = 0.0;
            for (int k = 1; k <= 3; k++) acc += Q[i][k] * Z[k][j];
            g_V[(i - 1) * 3 + (j - 1)] = (float)acc;
        }
}

__global__ void k_buildx0(const float* __restrict__ d, const float* __restrict__ ln1w,
                          const float* __restrict__ ln1b, int n) {
    int idx = blockIdx.x * blockDim.x + threadIdx.x;
    if (idx >= n * 36) return;
    int node = idx / 36, j = idx % 36;
    float val;
    if (j < 3) {
        float sc = g_pscale;
        float a = (d[node * 35 + 0] - g_pmean[0]) * sc;
        float b = (d[node * 35 + 1] - g_pmean[1]) * sc;
        float c = (d[node * 35 + 2] - g_pmean[2]) * sc;
        val = a * g_V[0 + j] + b * g_V[3 + j] + c * g_V[6 + j];
    } else if (j < 35) {
        val = (d[node * 35 + j] - g_fp[0]) / g_fp[1] * ln1w[j - 3] + ln1b[j - 3];
    } else val = 0.f;
    g_x0[idx] = val;
}

__global__ void k_hist(const int* __restrict__ ei, const int* __restrict__ et, int e) {
    int i = blockIdx.x * blockDim.x + threadIdx.x;
    if (i < e) atomicAdd(&g_count16[ei[e + i] * 16 + et[i]], 1);
}

__global__ void k_scanA(int ntot) {
    __shared__ int ws[8];
    int b = blockIdx.x, tid = threadIdx.x, lane = tid & 31, w = tid >> 5;
    int i = b * 256 + tid;
    int v = (i < ntot) ? g_count16[i] : 0;
    int x = v;
    for (int o = 1; o < 32; o <<= 1) {
        int y = __shfl_up_sync(0xffffffffu, x, o);
        if (lane >= o) x += y;
    }
    if (lane == 31) ws[w] = x;
    __syncthreads();
    if (tid == 0) {
        int run = 0;
        for (int j = 0; j < 8; j++) { int t = ws[j]; ws[j] = run; run += t; }
    }
    __syncthreads();
    int excl = x - v + ws[w];
    if (i < ntot) g_rp16[i] = excl;
    if (tid == 255) g_bsum[b] = excl + v;
}

__global__ void k_scanB(int nb) {
    __shared__ int sd[512];
    __shared__ int s_carry;
    int tid = threadIdx.x;
    if (tid == 0) s_carry = 0;
    __syncthreads();
    for (int b0 = 0; b0 < nb; b0 += 512) {
        int i = b0 + tid;
        int v = (i < nb) ? g_bsum[i] : 0;
        sd[tid] = v;
        __syncthreads();
        for (int o = 1; o < 512; o <<= 1) {
            int tv = (tid >= o) ? sd[tid - o] : 0;
            __syncthreads();
            sd[tid] += tv;
            __syncthreads();
        }
        int c = s_carry;
        if (i < nb) g_boff[i] = c + sd[tid] - v;
        __syncthreads();
        if (tid == 511) s_carry = c + sd[511];
        __syncthreads();
    }
}

__global__ void k_scanC(int ntot, int n, int e) {
    int i = blockIdx.x * blockDim.x + threadIdx.x;
    if (i >= ntot) return;
    int rp = g_rp16[i] + g_boff[i >> 8];
    g_cursor16[i] = rp;
    if ((i & 15) == 0) g_rowptr[i >> 4] = rp;
    if (i == 0) g_rowptr[n] = e;
}

__global__ void k_scatter(const int* __restrict__ ei, const int* __restrict__ et, int e) {
    int i = blockIdx.x * blockDim.x + threadIdx.x;
    if (i >= e) return;
    int r = et[i];
    int pos = atomicAdd(&g_cursor16[ei[e + i] * 16 + r], 1);
    g_epack[pos] = ei[i] | (r << 20);
}

// Tensor-core GEMM: xr[r] = x @ W[r] (fp16 in, fp32 acc), qv/kv fused epilogue.
template <int F, int STRIDE, int KP>
__global__ void k_gemm(const float* __restrict__ W, const float* __restrict__ qvec,
                       const float* __restrict__ kvec, int n) {
    __shared__ __half xs[128][56];
    __shared__ __half wt[32][56];
    __shared__ __half xout[128][36];
    __shared__ float sq[32], sk[32];
    int tid = threadIdx.x;
    int w = tid >> 5, lane = tid & 31, g = lane >> 2, t = lane & 3;
    int base = blockIdx.x * 128;
    const float* xbuf = (F == 35) ? g_x0 : g_x;

    for (int idx = tid; idx < 128 * KP; idx += 128) {
        int nl = idx / KP, f = idx % KP;
        int node = base + nl;
        float v = (f < F && node < n) ? xbuf[(size_t)node * STRIDE + f] : 0.f;
        xs[nl][f] = __float2half(v);
    }
    if (tid < 32) { sq[tid] = qvec[tid]; sk[tid] = kvec[tid]; }

    for (int r = 0; r < RREL; r++) {
        __syncthreads();
        for (int idx = tid; idx < 32 * KP; idx += 128) {
            int o = idx / KP, f = idx % KP;
            wt[o][f] = (f < F) ? __float2half(W[((size_t)r * F + f) * 32 + o]) : __float2half(0.f);
        }
        __syncthreads();
        for (int mt = 0; mt < 2; mt++) {
            int rowbase = w * 32 + mt * 16;
            float qp0 = 0, qp1 = 0, kp0 = 0, kp1 = 0;
            for (int nt = 0; nt < 4; nt++) {
                float d0 = 0, d1 = 0, d2 = 0, d3 = 0;
                #pragma unroll
                for (int ks = 0; ks < KP / 16; ks++) {
                    uint32_t a0 = *(const uint32_t*)&xs[rowbase + g][2 * t + ks * 16];
                    uint32_t a1 = *(const uint32_t*)&xs[rowbase + g + 8][2 * t + ks * 16];
                    uint32_t a2 = *(const uint32_t*)&xs[rowbase + g][2 * t + 8 + ks * 16];
                    uint32_t a3 = *(const uint32_t*)&xs[rowbase + g + 8][2 * t + 8 + ks * 16];
                    uint32_t b0 = *(const uint32_t*)&wt[nt * 8 + g][2 * t + ks * 16];
                    uint32_t b1 = *(const uint32_t*)&wt[nt * 8 + g][2 * t + 8 + ks * 16];
                    mma16816(d0, d1, d2, d3, a0, a1, a2, a3, b0, b1);
                }
                int c = nt * 8 + 2 * t;
                *(__half2*)&xout[rowbase + g][c] = __floats2half2_rn(d0, d1);
                *(__half2*)&xout[rowbase + g + 8][c] = __floats2half2_rn(d2, d3);
                qp0 += d0 * sq[c] + d1 * sq[c + 1];
                qp1 += d2 * sq[c] + d3 * sq[c + 1];
                kp0 += d0 * sk[c] + d1 * sk[c + 1];
                kp1 += d2 * sk[c] + d3 * sk[c + 1];
            }
            qp0 += __shfl_xor_sync(0xffffffffu, qp0, 1); qp0 += __shfl_xor_sync(0xffffffffu, qp0, 2);
            qp1 += __shfl_xor_sync(0xffffffffu, qp1, 1); qp1 += __shfl_xor_sync(0xffffffffu, qp1, 2);
            kp0 += __shfl_xor_sync(0xffffffffu, kp0, 1); kp0 += __shfl_xor_sync(0xffffffffu, kp0, 2);
            kp1 += __shfl_xor_sync(0xffffffffu, kp1, 1); kp1 += __shfl_xor_sync(0xffffffffu, kp1, 2);
            if (t == 0) {
                int n0 = base + rowbase + g, n1 = n0 + 8;
                if (n0 < n) { g_qv[n0 * 16 + r] = qp0; g_kv[n0 * 16 + r] = kp0; }
                if (n1 < n) { g_qv[n1 * 16 + r] = qp1; g_kv[n1 * 16 + r] = kp1; }
            }
        }
        __syncwarp();
        #pragma unroll
        for (int i = 0; i < 16; i++) {
            int rl = w * 32 + 2 * i + (lane >> 4);
            int node = base + rl;
            if (node < n) {
                uint32_t v = *(const uint32_t*)&xout[rl][(lane & 15) * 2];
                *(uint32_t*)&g_xr[((size_t)r * n + node) * 32 + (lane & 15) * 2] = v;
            }
        }
    }
}

// ONE-PASS edge kernel (identical to R10): edges now r-sorted within each dst row.
__global__ void k_edge(const float* __restrict__ bias, int layer, int n) {
    int warp = threadIdx.x >> 5, lane = threadIdx.x & 31;
    int node = blockIdx.x * 8 + warp;
    float h = 0.f;
    bool active = node < n;
    __shared__ float sh_qv[8][16];
    __shared__ float sh_h[8][32];
    if (active && lane < 16) sh_qv[warp][lane] = g_qv[node * 16 + lane];
    __syncwarp();
    if (active) {
        int beg = g_rowptr[node], end = g_rowptr[node + 1];
        float res = (layer > 0) ? g_x[(size_t)node * 32 + lane] : 0.f;
        if (end > beg) {
            int fq = lane & 3, eg = lane >> 2;
            float s = 0.f;
            float acc[8];
            #pragma unroll
            for (int j = 0; j < 8; j++) acc[j] = 0.f;
            for (int cb = beg; cb < end; cb += 32) {
                int i = cb + lane;
                float ee = 0.f;
                int ofs = 0;
                if (i < end) {
                    int p = g_epack[i];
                    int r = p >> 20, src = p & 0xFFFFF;
                    float a = sh_qv[warp][r] + g_kv[src * 16 + r];
                    a = (a > 0.f) ? a : 0.2f * a;
                    ee = __expf(a);
                    ofs = (r * n + src) * 32;
                }
                s += ee;
                int cnt = min(32, end - cb);
                for (int jb = 0; jb < cnt; jb += 8) {
                    int sl = jb + eg;
                    float pw = __shfl_sync(0xffffffffu, ee, sl & 31);
                    int of = __shfl_sync(0xffffffffu, ofs, sl & 31);
                    if (sl >= cnt) pw = 0.f;
                    uint4 v = *(const uint4*)&g_xr[(size_t)of + fq * 8];
                    float2 f0 = __half22float2(*(__half2*)&v.x);
                    float2 f1 = __half22float2(*(__half2*)&v.y);
                    float2 f2 = __half22float2(*(__half2*)&v.z);
                    float2 f3 = __half22float2(*(__half2*)&v.w);
                    acc[0] += pw * f0.x; acc[1] += pw * f0.y;
                    acc[2] += pw * f1.x; acc[3] += pw * f1.y;
                    acc[4] += pw * f2.x; acc[5] += pw * f2.y;
                    acc[6] += pw * f3.x; acc[7] += pw * f3.y;
                }
            }
            s = warpSumF(s);
            float inv = __fdividef(1.f, s + 1e-16f);
            #pragma unroll
            for (int j = 0; j < 8; j++) {
                acc[j] += __shfl_xor_sync(0xffffffffu, acc[j], 4);
                acc[j] += __shfl_xor_sync(0xffffffffu, acc[j], 8);
                acc[j] += __shfl_xor_sync(0xffffffffu, acc[j], 16);
            }
            if (eg == 0) {
                #pragma unroll
                for (int j = 0; j < 8; j++) sh_h[warp][fq * 8 + j] = acc[j] * inv;
            }
            __syncwarp();
            h = sh_h[warp][lane];
        }
        h += bias[lane] + res;
        g_h[(size_t)node * 32 + lane] = h;
    }
    double v = active ? (double)h : 0.0;
    double v2 = active ? (double)h * (double)h : 0.0;
    v = warpSumD(v); v2 = warpSumD(v2);
    __shared__ double sh[2][8];
    if (lane == 0) { sh[0][warp] = v; sh[1][warp] = v2; }
    __syncthreads();
    if (threadIdx.x == 0) {
        double a = 0, b = 0;
        for (int ww = 0; ww < 8; ww++) { a += sh[0][ww]; b += sh[1][ww]; }
        atomicAdd(&g_stats[layer][0], a);
        atomicAdd(&g_stats[layer][1], b);
    }
}

__global__ void k_lnact(const float* __restrict__ lnw, const float* __restrict__ lnb,
                        int layer, int n, int dopool) {
    __shared__ float s_mu, s_std;
    if (threadIdx.x == 0) {
        double cnt = (double)n * 32.0;
        double mu = g_stats[layer][0] / cnt;
        double var = g_stats[layer][1] / cnt - mu * mu;
        if (var < 0.0) var = 0.0;
        s_mu = (float)mu;
        s_std = (float)sqrt(var) + 1e-5f;
    }
    __syncthreads();
    float mu = s_mu, stdpe = s_std;
    int f = threadIdx.x & 31;
    float w = lnw[f], b = lnb[f];
    double acc = 0.0;
    int total = n * 32;
    for (int i = blockIdx.x * blockDim.x + threadIdx.x; i < total; i += gridDim.x * blockDim.x) {
        float t = (g_h[i] - mu) / stdpe * w + b;
        float sig = 1.f / (1.f + __expf(-t));
        float xo = t * sig;
        g_x[i] = xo;
        acc += (double)xo;
    }
    if (dopool) {
        __shared__ double shd[8][32];
        int warp = threadIdx.x >> 5;
        shd[warp][f] = acc;
        __syncthreads();
        if (warp == 0) {
            double a = 0;
            for (int ww = 0; ww < 8; ww++) a += shd[ww][f];
            atomicAdd(&g_pool[f], a);
        }
    }
}

__global__ void k_final(const float* __restrict__ W, const float* __restrict__ b,
                        float* __restrict__ out, int n) {
    __shared__ float x3[32];
    if (threadIdx.x < 32) x3[threadIdx.x] = (float)(g_pool[threadIdx.x] / (double)n);
    __syncthreads();
    int j = threadIdx.x;
    if (j < 256) {
        float acc = b[j];
        #pragma unroll
        for (int o = 0; o < 32; o++) acc += x3[o] * W[j * 32 + o];
        float sig = 1.f / (1.f + expf(-acc));
        out[j] = acc * sig;
    }
}

extern "C" void kernel_launch(void* const* d_in, const int* in_sizes, int n_in,
                              void* d_out, int out_size) {
    const float* db1  = (const float*)d_in[0];
    const int*   ei   = (const int*)d_in[2];
    const int*   et   = (const int*)d_in[3];
    const float* W0   = (const float*)d_in[6];
    const float* q0   = (const float*)d_in[7];
    const float* k0   = (const float*)d_in[8];
    const float* b0   = (const float*)d_in[9];
    const float* Ws   = (const float*)d_in[10];
    const float* qs   = (const float*)d_in[11];
    const float* ks   = (const float*)d_in[12];
    const float* bs   = (const float*)d_in[13];
    const float* lnw  = (const float*)d_in[14];
    const float* lnb  = (const float*)d_in[15];
    const float* ln1w = (const float*)d_in[16];
    const float* ln1b = (const float*)d_in[17];
    const float* l1W  = (const float*)d_in[18];
    const float* l1b  = (const float*)d_in[19];
    float* out = (float*)d_out;
    int n = in_sizes[0] / 35;
    int e = in_sizes[3];
    int ntot = n * 16;
    int nb16 = (ntot + 255) / 256;

    k_zero<<<512, 256>>>();
    k_stats<<<512, 256>>>(db1, n);
    k_eigh<<<1, 1>>>(n);
    k_buildx0<<<(n * 36 + 255) / 256, 256>>>(db1, ln1w, ln1b, n);

    k_hist<<<(e + 255) / 256, 256>>>(ei, et, e);
    k_scanA<<<nb16, 256>>>(ntot);
    k_scanB<<<1, 512>>>(nb16);
    k_scanC<<<nb16, 256>>>(ntot, n, e);
    k_scatter<<<(e + 255) / 256, 256>>>(ei, et, e);

    int gg = (n + 127) / 128;
    for (int l = 0; l < NLAY; l++) {
        const float* bias = (l == 0) ? b0 : bs + (l - 1) * 32;
        if (l == 0) {
            k_gemm<35, 36, 48><<<gg, 128>>>(W0, q0, k0, n);
        } else {
            k_gemm<32, 32, 32><<<gg, 128>>>(Ws + (size_t)(l - 1) * RREL * 32 * 32,
                                            qs + (l - 1) * 32, ks + (l - 1) * 32, n);
        }
        k_edge<<<(n + 7) / 8, 256>>>(bias, l, n);
        k_lnact<<<512, 256>>>(lnw + l * 32, lnb + l * 32, l, n, (l == NLAY - 1) ? 1 : 0);
    }
    k_final<<<1, 256>>>(l1W, l1b, out, n);
}